// round 14
// baseline (speedup 1.0000x reference)
#include <cuda_runtime.h>
#include <cstdint>
#include <math.h>

// Problem constants
#define TT    4096
#define DIN   4096
#define DOUT  4096
#define NE    8
#define N2    320    // [svh(256) | gate(64)]
#define KEXT  272    // 256 + 8 (w->bias) + 8 zero pad -> 17 chunks of 16
#define KSPL  4
#define CSPL  2048   // cols [0,CSPL) FFMA2, [CSPL,4096) tf32 mma

// Scratch (device globals; allocation is forbidden)
__device__ float g_p[KSPL * TT * N2];
__device__ float g_rl[TT * NE];
__device__ float g_w[TT * NE];
__device__ float g_aext[TT * KEXT];
__device__ float g_bext[DOUT * KEXT];
__device__ float g_xt[TT * DIN];               // x pre-rounded to tf32
__device__ float g_wt[(DOUT - CSPL) * DIN];    // shw tf32-half pre-rounded

// ---------------- f32x2 packed-FMA helpers ----------
__device__ __forceinline__ void fma2(uint64_t& d, uint64_t a, uint64_t b) {
    asm("fma.rn.f32x2 %0, %1, %2, %0;" : "+l"(d) : "l"(a), "l"(b));
}
__device__ __forceinline__ uint64_t dup32(float v) {
    uint64_t r;
    asm("mov.b64 %0, {%1, %1};" : "=l"(r) : "f"(v));
    return r;
}
__device__ __forceinline__ float2 unpk(uint64_t v) {
    float2 r;
    asm("mov.b64 {%0, %1}, %2;" : "=f"(r.x), "=f"(r.y) : "l"(v));
    return r;
}
// ---------------- tf32 mma helpers ----------
__device__ __forceinline__ uint32_t smem_u32(const void* p) {
    uint32_t a;
    asm("{ .reg .u64 t; cvta.to.shared.u64 t, %1; cvt.u32.u64 %0, t; }" : "=r"(a) : "l"(p));
    return a;
}
__device__ __forceinline__ void cpa16(uint32_t dst, const void* src) {
    asm volatile("cp.async.cg.shared.global [%0], [%1], 16;" :: "r"(dst), "l"(src));
}
__device__ __forceinline__ uint32_t f2tf32(float f) {
    uint32_t r;
    asm("cvt.rna.tf32.f32 %0, %1;" : "=r"(r) : "f"(f));
    return r;
}
__device__ __forceinline__ void mma8(float* c, const uint32_t* a, const uint32_t* b) {
    asm volatile(
        "mma.sync.aligned.m16n8k8.row.col.f32.tf32.tf32.f32 "
        "{%0,%1,%2,%3}, {%4,%5,%6,%7}, {%8,%9}, {%0,%1,%2,%3};"
        : "+f"(c[0]), "+f"(c[1]), "+f"(c[2]), "+f"(c[3])
        : "r"(a[0]), "r"(a[1]), "r"(a[2]), "r"(a[3]), "r"(b[0]), "r"(b[1]));
}

// ---------------------------------------------------------------------------
// Pre-round an fp32 array to tf32 (rna), elementwise, 4 per thread.
// ---------------------------------------------------------------------------
__global__ void tf32_round(const float* __restrict__ in, float* __restrict__ outp,
                           int n4) {
    int i = blockIdx.x * blockDim.x + threadIdx.x;
    if (i >= n4) return;
    float4 v = ((const float4*)in)[i];
    uint4 r;
    r.x = f2tf32(v.x); r.y = f2tf32(v.y); r.z = f2tf32(v.z); r.w = f2tf32(v.w);
    ((uint4*)outp)[i] = r;
}

// ---------------------------------------------------------------------------
__global__ void bext_kernel(const float* __restrict__ u, const float* __restrict__ eb) {
    int idx = blockIdx.x * blockDim.x + threadIdx.x;
    if (idx >= DOUT * KEXT) return;
    int n = idx / KEXT;
    int k = idx - n * KEXT;
    float v = 0.f;
    if (k < 256) {
        int e = k >> 5, r = k & 31;
        v = u[(e * DOUT + n) * 32 + r];
    } else if (k < 264) {
        v = eb[(k - 256) * DOUT + n];
    }
    g_bext[idx] = v;
}

// ---------------------------------------------------------------------------
// Split-K fused small GEMM (R12-proven verbatim)
// ---------------------------------------------------------------------------
__global__ __launch_bounds__(256) void skgemm(const float* __restrict__ A,
                                              const float* __restrict__ svh,
                                              const float* __restrict__ gate) {
    constexpr int BK = 16;
    constexpr int LAs = 132, LBs = 68;
    __shared__ float As[2][BK][LAs];
    __shared__ float Bs[2][BK][LBs];
    const int tid = threadIdx.x;
    const int tx = tid & 15, ty = tid >> 4;
    const int arow = tid >> 2;
    const int acol = (tid & 3) * 4;
    const int n0 = blockIdx.x * 64;
    const int t0 = blockIdx.y * 128;
    const int koff = blockIdx.z * (DIN / KSPL);

    const float* Ag = A + (size_t)(t0 + arow) * DIN + koff + acol;
    const float* Bg = (blockIdx.x < 4)
                    ? svh + (size_t)(n0 + arow) * DIN + koff + acol
                    : gate + (size_t)arow * DIN + koff + acol;

    uint64_t acc[4][4];
    #pragma unroll
    for (int i = 0; i < 4; i++)
        #pragma unroll
        for (int j = 0; j < 4; j++) acc[i][j] = 0ull;

    float4 av[2], bv;
    auto sts = [&](int buf) {
        #pragma unroll
        for (int p = 0; p < 2; p++) {
            As[buf][acol + 0][arow + p * 64] = av[p].x;
            As[buf][acol + 1][arow + p * 64] = av[p].y;
            As[buf][acol + 2][arow + p * 64] = av[p].z;
            As[buf][acol + 3][arow + p * 64] = av[p].w;
        }
        Bs[buf][acol + 0][arow] = bv.x;
        Bs[buf][acol + 1][arow] = bv.y;
        Bs[buf][acol + 2][arow] = bv.z;
        Bs[buf][acol + 3][arow] = bv.w;
    };

    av[0] = *(const float4*)(Ag);
    av[1] = *(const float4*)(Ag + (size_t)64 * DIN);
    bv = *(const float4*)(Bg);
    sts(0);
    __syncthreads();

    const int nk = DIN / KSPL / BK;
    for (int kt = 0; kt < nk; kt++) {
        const int cur = kt & 1;
        if (kt + 1 < nk) {
            av[0] = *(const float4*)(Ag + (kt + 1) * BK);
            av[1] = *(const float4*)(Ag + (kt + 1) * BK + (size_t)64 * DIN);
            bv = *(const float4*)(Bg + (kt + 1) * BK);
        }
        #pragma unroll
        for (int kk = 0; kk < BK; kk++) {
            uint64_t a2[4], bd[4];
            {
                ulonglong2 p0 = *(const ulonglong2*)&As[cur][kk][ty * 8];
                ulonglong2 p1 = *(const ulonglong2*)&As[cur][kk][ty * 8 + 4];
                a2[0] = p0.x; a2[1] = p0.y; a2[2] = p1.x; a2[3] = p1.y;
            }
            #pragma unroll
            for (int j = 0; j < 4; j++)
                bd[j] = dup32(Bs[cur][kk][tx * 4 + j]);
            #pragma unroll
            for (int i = 0; i < 4; i++)
                #pragma unroll
                for (int j = 0; j < 4; j++)
                    fma2(acc[i][j], a2[i], bd[j]);
        }
        if (kt + 1 < nk) {
            sts(cur ^ 1);
            __syncthreads();
        }
    }

    float* outp = g_p + (size_t)blockIdx.z * TT * N2;
    const int row0 = t0 + ty * 8;
    const int col0 = n0 + tx * 4;
    #pragma unroll
    for (int i = 0; i < 4; i++)
        #pragma unroll
        for (int j = 0; j < 4; j++) {
            float2 v = unpk(acc[i][j]);
            outp[(size_t)(row0 + 2 * i) * N2 + col0 + j] = v.x;
            outp[(size_t)(row0 + 2 * i + 1) * N2 + col0 + j] = v.y;
        }
}

// ---------------------------------------------------------------------------
__global__ void rl_kernel() {
    int idx = blockIdx.x * blockDim.x + threadIdx.x;
    if (idx >= TT * NE) return;
    int t = idx >> 3, e = idx & 7;
    const float* p0 = g_p + (size_t)t * N2 + 256 + e * 8;
    float s = 0.f;
    #pragma unroll
    for (int r = 0; r < 8; r++) {
        float gl = 0.f;
        #pragma unroll
        for (int ks = 0; ks < KSPL; ks++)
            gl += p0[(size_t)ks * TT * N2 + r];
        s += gl * gl;
    }
    g_rl[idx] = sqrtf(s);
}

__global__ void finalize_w() {
    int t = blockIdx.x * blockDim.x + threadIdx.x;
    if (t >= TT) return;
    float rl[NE];
    #pragma unroll
    for (int e = 0; e < NE; e++) rl[e] = g_rl[t * NE + e];
    int i1 = 0;
    #pragma unroll
    for (int e = 1; e < NE; e++) if (rl[e] > rl[i1]) i1 = e;
    int i2 = (i1 == 0) ? 1 : 0;
    #pragma unroll
    for (int e = 0; e < NE; e++) if (e != i1 && rl[e] > rl[i2]) i2 = e;
    float e2 = expf(rl[i2] - rl[i1]);
    float inv = 1.f / (1.f + e2);
    #pragma unroll
    for (int e = 0; e < NE; e++)
        g_w[t * NE + e] = (e == i1) ? inv : ((e == i2) ? e2 * inv : 0.f);
}

__global__ void aext_build() {
    int idx = blockIdx.x * blockDim.x + threadIdx.x;
    if (idx >= TT * (KEXT / 4)) return;
    int t = idx / (KEXT / 4);
    int k4 = idx - t * (KEXT / 4);
    float4 v;
    if (k4 < 64) {
        const float* p0 = g_p + (size_t)t * N2 + k4 * 4;
        v = *(const float4*)(p0);
        #pragma unroll
        for (int ks = 1; ks < KSPL; ks++) {
            float4 sp = *(const float4*)(p0 + (size_t)ks * TT * N2);
            v.x += sp.x; v.y += sp.y; v.z += sp.z; v.w += sp.w;
        }
        float we = g_w[t * NE + (k4 >> 3)];
        v.x *= we; v.y *= we; v.z *= we; v.w *= we;
    } else if (k4 < 66) {
        const float* wp = g_w + t * NE + (k4 - 64) * 4;
        v = make_float4(wp[0], wp[1], wp[2], wp[3]);
    } else {
        v = make_float4(0.f, 0.f, 0.f, 0.f);
    }
    *(float4*)(g_aext + (size_t)t * KEXT + k4 * 4) = v;
}

// ---------------------------------------------------------------------------
// FFMA2 shared-path GEMM, cols [0, CSPL) (R10/R12-proven structure)
// ---------------------------------------------------------------------------
#define LA 132
#define LBR 144

__global__ __launch_bounds__(256, 2) void seg0_gemm(const float* __restrict__ X,
                                                    const float* __restrict__ W,
                                                    const float* __restrict__ Bias,
                                                    float* __restrict__ C) {
    constexpr int BK = 16;
    __shared__ __align__(16) float As[2][BK][LA];
    __shared__ __align__(16) float Bs[2][BK][LBR];
    const int tid = threadIdx.x;
    const int tx = tid & 15, ty = tid >> 4;
    const int arow = tid >> 2;
    const int acol = (tid & 3) * 4;
    const int bslot = ((arow >> 3) * 9) + (arow & 7);

    uint64_t acc[4][8];
    #pragma unroll
    for (int i = 0; i < 4; i++)
        #pragma unroll
        for (int j = 0; j < 8; j++) acc[i][j] = 0ull;

    float4 av[2], bv[2];
    auto sts = [&](int buf) {
        #pragma unroll
        for (int p = 0; p < 2; p++) {
            As[buf][acol + 0][arow + p * 64] = av[p].x;
            As[buf][acol + 1][arow + p * 64] = av[p].y;
            As[buf][acol + 2][arow + p * 64] = av[p].z;
            As[buf][acol + 3][arow + p * 64] = av[p].w;
            Bs[buf][acol + 0][bslot + p * 72] = bv[p].x;
            Bs[buf][acol + 1][bslot + p * 72] = bv[p].y;
            Bs[buf][acol + 2][bslot + p * 72] = bv[p].z;
            Bs[buf][acol + 3][bslot + p * 72] = bv[p].w;
        }
    };

    const float* Ag = X + (size_t)(blockIdx.y * 128 + arow) * DIN + acol;
    const float* Bg = W + (size_t)(blockIdx.x * 128 + arow) * DIN + acol;

    av[0] = *(const float4*)(Ag);
    av[1] = *(const float4*)(Ag + (size_t)64 * DIN);
    bv[0] = *(const float4*)(Bg);
    bv[1] = *(const float4*)(Bg + (size_t)64 * DIN);
    sts(0);
    __syncthreads();

    const int nk = DIN / BK;
    for (int kt = 0; kt < nk; kt++) {
        const int cur = kt & 1;
        if (kt + 1 < nk) {
            av[0] = *(const float4*)(Ag + (kt + 1) * BK);
            av[1] = *(const float4*)(Ag + (kt + 1) * BK + (size_t)64 * DIN);
            bv[0] = *(const float4*)(Bg + (kt + 1) * BK);
            bv[1] = *(const float4*)(Bg + (kt + 1) * BK + (size_t)64 * DIN);
        }
        #pragma unroll
        for (int kk = 0; kk < BK; kk++) {
            uint64_t a2[4], bd[8];
            {
                ulonglong2 p0 = *(const ulonglong2*)&As[cur][kk][ty * 8];
                ulonglong2 p1 = *(const ulonglong2*)&As[cur][kk][ty * 8 + 4];
                a2[0] = p0.x; a2[1] = p0.y; a2[2] = p1.x; a2[3] = p1.y;
            }
            #pragma unroll
            for (int j = 0; j < 8; j++)
                bd[j] = dup32(Bs[cur][kk][tx * 9 + j]);
            #pragma unroll
            for (int i = 0; i < 4; i++)
                #pragma unroll
                for (int j = 0; j < 8; j++)
                    fma2(acc[i][j], a2[i], bd[j]);
        }
        if (kt + 1 < nk) {
            sts(cur ^ 1);
            __syncthreads();
        }
    }

    const int row0 = blockIdx.y * 128 + ty * 8;
    const int col0 = blockIdx.x * 128 + tx * 8;
    #pragma unroll
    for (int i = 0; i < 4; i++)
        #pragma unroll
        for (int j = 0; j < 8; j++) {
            float2 v = unpk(acc[i][j]);
            float b = Bias[col0 + j];
            C[(size_t)(row0 + 2 * i) * DOUT + col0 + j] = v.x + b;
            C[(size_t)(row0 + 2 * i + 1) * DOUT + col0 + j] = v.y + b;
        }
}

// ---------------------------------------------------------------------------
// FFMA2 expert add-GEMM: out += aext @ bext^T (K=272), cols [coff + 128*bx).
// ---------------------------------------------------------------------------
__global__ __launch_bounds__(256, 2) void exp_gemm(float* __restrict__ C, int coff) {
    constexpr int BK = 16;
    __shared__ __align__(16) float As[2][BK][LA];
    __shared__ __align__(16) float Bs[2][BK][LBR];
    const int tid = threadIdx.x;
    const int tx = tid & 15, ty = tid >> 4;
    const int arow = tid >> 2;
    const int acol = (tid & 3) * 4;
    const int bslot = ((arow >> 3) * 9) + (arow & 7);
    const int nb0 = coff + blockIdx.x * 128;

    uint64_t acc[4][8];
    #pragma unroll
    for (int i = 0; i < 4; i++)
        #pragma unroll
        for (int j = 0; j < 8; j++) acc[i][j] = 0ull;

    float4 av[2], bv[2];
    auto sts = [&](int buf) {
        #pragma unroll
        for (int p = 0; p < 2; p++) {
            As[buf][acol + 0][arow + p * 64] = av[p].x;
            As[buf][acol + 1][arow + p * 64] = av[p].y;
            As[buf][acol + 2][arow + p * 64] = av[p].z;
            As[buf][acol + 3][arow + p * 64] = av[p].w;
            Bs[buf][acol + 0][bslot + p * 72] = bv[p].x;
            Bs[buf][acol + 1][bslot + p * 72] = bv[p].y;
            Bs[buf][acol + 2][bslot + p * 72] = bv[p].z;
            Bs[buf][acol + 3][bslot + p * 72] = bv[p].w;
        }
    };

    const float* Ag = g_aext + (size_t)(blockIdx.y * 128 + arow) * KEXT + acol;
    const float* Bg = g_bext + (size_t)(nb0 + arow) * KEXT + acol;

    av[0] = *(const float4*)(Ag);
    av[1] = *(const float4*)(Ag + (size_t)64 * KEXT);
    bv[0] = *(const float4*)(Bg);
    bv[1] = *(const float4*)(Bg + (size_t)64 * KEXT);
    sts(0);
    __syncthreads();

    const int nk = KEXT / BK;   // 17
    for (int kt = 0; kt < nk; kt++) {
        const int cur = kt & 1;
        if (kt + 1 < nk) {
            av[0] = *(const float4*)(Ag + (kt + 1) * BK);
            av[1] = *(const float4*)(Ag + (kt + 1) * BK + (size_t)64 * KEXT);
            bv[0] = *(const float4*)(Bg + (kt + 1) * BK);
            bv[1] = *(const float4*)(Bg + (kt + 1) * BK + (size_t)64 * KEXT);
        }
        #pragma unroll
        for (int kk = 0; kk < BK; kk++) {
            uint64_t a2[4], bd[8];
            {
                ulonglong2 p0 = *(const ulonglong2*)&As[cur][kk][ty * 8];
                ulonglong2 p1 = *(const ulonglong2*)&As[cur][kk][ty * 8 + 4];
                a2[0] = p0.x; a2[1] = p0.y; a2[2] = p1.x; a2[3] = p1.y;
            }
            #pragma unroll
            for (int j = 0; j < 8; j++)
                bd[j] = dup32(Bs[cur][kk][tx * 9 + j]);
            #pragma unroll
            for (int i = 0; i < 4; i++)
                #pragma unroll
                for (int j = 0; j < 8; j++)
                    fma2(acc[i][j], a2[i], bd[j]);
        }
        if (kt + 1 < nk) {
            sts(cur ^ 1);
            __syncthreads();
        }
    }

    const int row0 = blockIdx.y * 128 + ty * 8;
    const int col0 = nb0 + tx * 8;
    #pragma unroll
    for (int i = 0; i < 4; i++)
        #pragma unroll
        for (int j = 0; j < 8; j++) {
            float2 v = unpk(acc[i][j]);
            C[(size_t)(row0 + 2 * i) * DOUT + col0 + j] += v.x;
            C[(size_t)(row0 + 2 * i + 1) * DOUT + col0 + j] += v.y;
        }
}

// ---------------------------------------------------------------------------
// tf32 mma.sync GEMM, operands PRE-ROUNDED (no cvt in loop).
// ---------------------------------------------------------------------------
#define TSS 36
#define TSTAGE ((256 + 128) * TSS)
#define TSMEM (2 * TSTAGE * 4)

__global__ __launch_bounds__(256, 1)
void ttgemm(const float* __restrict__ A, const float* __restrict__ B,
            int lda, int ldb, int nch,
            float* __restrict__ C, int ldc, const float* __restrict__ bias) {
    extern __shared__ __align__(16) float sm[];
    const int tid = threadIdx.x;
    const int m0 = blockIdx.y * 256, n0 = blockIdx.x * 128;

    auto load_stage = [&](int c, int buf) {
        const int kc0 = c * 32;
        float* sA = sm + buf * TSTAGE;
        float* sB = sA + 256 * TSS;
        #pragma unroll
        for (int i = 0; i < 8; i++) {
            int idx = tid + i * 256;
            int m = idx >> 3, kc = (idx & 7) * 4;
            cpa16(smem_u32(sA + m * TSS + kc), A + (size_t)(m0 + m) * lda + kc0 + kc);
        }
        #pragma unroll
        for (int i = 0; i < 4; i++) {
            int idx = tid + i * 256;
            int nn = idx >> 3, kc = (idx & 7) * 4;
            cpa16(smem_u32(sB + nn * TSS + kc), B + (size_t)(n0 + nn) * ldb + kc0 + kc);
        }
        asm volatile("cp.async.commit_group;" ::: "memory");
    };

    float acc[4][8][4];
    #pragma unroll
    for (int i = 0; i < 4; i++)
        #pragma unroll
        for (int j = 0; j < 8; j++)
            #pragma unroll
            for (int q = 0; q < 4; q++) acc[i][j][q] = 0.f;

    const int warp = tid >> 5, lane = tid & 31;
    const int qr = lane >> 2, qc = lane & 3;
    const int wm = warp >> 1, wn = warp & 1;

    load_stage(0, 0);
    load_stage(1, 1);

    #pragma unroll 1
    for (int c = 0; c < nch; c++) {
        const int buf = c & 1;
        if (c + 1 < nch) asm volatile("cp.async.wait_group 1;" ::: "memory");
        else             asm volatile("cp.async.wait_group 0;" ::: "memory");
        __syncthreads();
        const uint32_t* sA = (const uint32_t*)(sm + buf * TSTAGE) + (wm * 64 + qr) * TSS + qc;
        const uint32_t* sB = (const uint32_t*)(sm + buf * TSTAGE) + 256 * TSS + (wn * 64 + qr) * TSS + qc;

        #pragma unroll
        for (int kk = 0; kk < 4; kk++) {
            uint32_t af[4][4], bf[8][2];
            #pragma unroll
            for (int mt = 0; mt < 4; mt++) {
                const uint32_t* p = sA + mt * 16 * TSS + kk * 8;
                af[mt][0] = p[0];
                af[mt][1] = p[8 * TSS];
                af[mt][2] = p[4];
                af[mt][3] = p[8 * TSS + 4];
            }
            #pragma unroll
            for (int nt = 0; nt < 8; nt++) {
                const uint32_t* p = sB + nt * 8 * TSS + kk * 8;
                bf[nt][0] = p[0];
                bf[nt][1] = p[4];
            }
            #pragma unroll
            for (int mt = 0; mt < 4; mt++)
                #pragma unroll
                for (int nt = 0; nt < 8; nt++)
                    mma8(acc[mt][nt], af[mt], bf[nt]);
        }
        __syncthreads();
        if (c + 2 < nch) load_stage(c + 2, buf);
    }

    const int rbase = m0 + wm * 64;
    const int cbase = n0 + wn * 64;
    #pragma unroll
    for (int mt = 0; mt < 4; mt++) {
        #pragma unroll
        for (int nt = 0; nt < 8; nt++) {
            const int r = rbase + mt * 16 + qr;
            const int col = cbase + nt * 8 + qc * 2;
            float bx = bias[col], by = bias[col + 1];
            float2 v0 = make_float2(acc[mt][nt][0] + bx, acc[mt][nt][1] + by);
            float2 v1 = make_float2(acc[mt][nt][2] + bx, acc[mt][nt][3] + by);
            *(float2*)(C + (size_t)r * ldc + col) = v0;
            *(float2*)(C + (size_t)(r + 8) * ldc + col) = v1;
        }
    }
}

// ---------------------------------------------------------------------------
extern "C" void kernel_launch(void* const* d_in, const int* in_sizes, int n_in,
                              void* d_out, int out_size) {
    const float* x    = (const float*)d_in[0];
    const float* gate = (const float*)d_in[1];
    const float* shw  = (const float*)d_in[2];
    const float* shb  = (const float*)d_in[3];
    const float* u    = (const float*)d_in[4];
    const float* svh  = (const float*)d_in[5];
    const float* eb   = (const float*)d_in[6];
    float* out = (float*)d_out;

    static cudaStream_t s1, s2;
    static cudaEvent_t e0, e1, e2;
    static int once = 0;
    if (!once) {
        cudaStreamCreateWithFlags(&s1, cudaStreamNonBlocking);
        cudaStreamCreateWithFlags(&s2, cudaStreamNonBlocking);
        cudaEventCreateWithFlags(&e0, cudaEventDisableTiming);
        cudaEventCreateWithFlags(&e1, cudaEventDisableTiming);
        cudaEventCreateWithFlags(&e2, cudaEventDisableTiming);
        cudaFuncSetAttribute(ttgemm, cudaFuncAttributeMaxDynamicSharedMemorySize, TSMEM);
        cudaFuncSetAttribute(seg0_gemm,
                             cudaFuncAttributePreferredSharedMemoryCarveout, 100);
        cudaFuncSetAttribute(exp_gemm,
                             cudaFuncAttributePreferredSharedMemoryCarveout, 100);
        once = 1;
    }

    // fork
    cudaEventRecord(e0, 0);
    cudaStreamWaitEvent(s1, e0, 0);
    cudaStreamWaitEvent(s2, e0, 0);

    // s1: small chain -> aext
    bext_kernel<<<(DOUT * KEXT + 255) / 256, 256, 0, s1>>>(u, eb);
    skgemm<<<dim3(N2 / 64, TT / 128, KSPL), 256, 0, s1>>>(x, svh, gate);
    rl_kernel<<<(TT * NE + 255) / 256, 256, 0, s1>>>();
    finalize_w<<<(TT + 255) / 256, 256, 0, s1>>>();
    aext_build<<<(TT * (KEXT / 4) + 255) / 256, 256, 0, s1>>>();
    cudaEventRecord(e1, s1);

    // s2: pre-round operands, tf32 mma half (cols [CSPL,4096)), its expert add
    tf32_round<<<(TT * DIN / 4 + 255) / 256, 256, 0, s2>>>(x, g_xt, TT * DIN / 4);
    tf32_round<<<((DOUT - CSPL) * DIN / 4 + 255) / 256, 256, 0, s2>>>(
        shw + (size_t)CSPL * DIN, g_wt, (DOUT - CSPL) * DIN / 4);
    ttgemm<<<dim3((DOUT - CSPL) / 128, TT / 256), 256, TSMEM, s2>>>(
        g_xt, g_wt, DIN, DIN, DIN / 32, out + CSPL, DOUT, shb + CSPL);
    cudaStreamWaitEvent(s2, e1, 0);
    exp_gemm<<<dim3((DOUT - CSPL) / 128, TT / 128), 256, 0, s2>>>(out, CSPL);
    cudaEventRecord(e2, s2);

    // default: FFMA2 half (cols [0,CSPL)), its expert add
    seg0_gemm<<<dim3(CSPL / 128, TT / 128), 256>>>(x, shw, shb, out);
    cudaStreamWaitEvent(0, e1, 0);
    exp_gemm<<<dim3(CSPL / 128, TT / 128), 256>>>(out, 0);

    // join s2 back to origin
    cudaStreamWaitEvent(0, e2, 0);
}

// round 15
// speedup vs baseline: 6.5568x; 6.5568x over previous
#include <cuda_runtime.h>
#include <cstdint>
#include <math.h>

// Problem constants
#define TT    4096
#define DIN   4096
#define DOUT  4096
#define NE    8
#define N2    320    // [svh(256) | gate(64)]
#define KEXT  272    // 256 + 8 (w->bias) + 8 zero pad -> 17 chunks of 16
#define KSPL  4
#define CSPL  2304   // cols [0,CSPL) FFMA2, [CSPL,4096) tf32 mma

// Scratch (device globals; allocation is forbidden)
__device__ float g_p[KSPL * TT * N2];
__device__ float g_rl[TT * NE];
__device__ float g_w[TT * NE];
__device__ float g_aext[TT * KEXT];
__device__ float g_bext[DOUT * KEXT];

// ---------------- f32x2 packed-FMA helpers ----------
__device__ __forceinline__ void fma2(uint64_t& d, uint64_t a, uint64_t b) {
    asm("fma.rn.f32x2 %0, %1, %2, %0;" : "+l"(d) : "l"(a), "l"(b));
}
__device__ __forceinline__ uint64_t dup32(float v) {
    uint64_t r;
    asm("mov.b64 %0, {%1, %1};" : "=l"(r) : "f"(v));
    return r;
}
__device__ __forceinline__ float2 unpk(uint64_t v) {
    float2 r;
    asm("mov.b64 {%0, %1}, %2;" : "=f"(r.x), "=f"(r.y) : "l"(v));
    return r;
}
// ---------------- tf32 mma helpers (R6-proven) ----------
__device__ __forceinline__ uint32_t smem_u32(const void* p) {
    uint32_t a;
    asm("{ .reg .u64 t; cvta.to.shared.u64 t, %1; cvt.u32.u64 %0, t; }" : "=r"(a) : "l"(p));
    return a;
}
__device__ __forceinline__ void cpa16(uint32_t dst, const void* src) {
    asm volatile("cp.async.cg.shared.global [%0], [%1], 16;" :: "r"(dst), "l"(src));
}
__device__ __forceinline__ uint32_t f2tf32(float f) {
    uint32_t r;
    asm("cvt.rna.tf32.f32 %0, %1;" : "=r"(r) : "f"(f));
    return r;
}
__device__ __forceinline__ void mma8(float* c, const uint32_t* a, const uint32_t* b) {
    asm volatile(
        "mma.sync.aligned.m16n8k8.row.col.f32.tf32.tf32.f32 "
        "{%0,%1,%2,%3}, {%4,%5,%6,%7}, {%8,%9}, {%0,%1,%2,%3};"
        : "+f"(c[0]), "+f"(c[1]), "+f"(c[2]), "+f"(c[3])
        : "r"(a[0]), "r"(a[1]), "r"(a[2]), "r"(a[3]), "r"(b[0]), "r"(b[1]));
}

// ---------------------------------------------------------------------------
__global__ void bext_kernel(const float* __restrict__ u, const float* __restrict__ eb) {
    int idx = blockIdx.x * blockDim.x + threadIdx.x;
    if (idx >= DOUT * KEXT) return;
    int n = idx / KEXT;
    int k = idx - n * KEXT;
    float v = 0.f;
    if (k < 256) {
        int e = k >> 5, r = k & 31;
        v = u[(e * DOUT + n) * 32 + r];
    } else if (k < 264) {
        v = eb[(k - 256) * DOUT + n];
    }
    g_bext[idx] = v;
}

// ---------------------------------------------------------------------------
// Split-K fused small GEMM (R12-proven verbatim)
// ---------------------------------------------------------------------------
__global__ __launch_bounds__(256) void skgemm(const float* __restrict__ A,
                                              const float* __restrict__ svh,
                                              const float* __restrict__ gate) {
    constexpr int BK = 16;
    constexpr int LAs = 132, LBs = 68;
    __shared__ float As[2][BK][LAs];
    __shared__ float Bs[2][BK][LBs];
    const int tid = threadIdx.x;
    const int tx = tid & 15, ty = tid >> 4;
    const int arow = tid >> 2;
    const int acol = (tid & 3) * 4;
    const int n0 = blockIdx.x * 64;
    const int t0 = blockIdx.y * 128;
    const int koff = blockIdx.z * (DIN / KSPL);

    const float* Ag = A + (size_t)(t0 + arow) * DIN + koff + acol;
    const float* Bg = (blockIdx.x < 4)
                    ? svh + (size_t)(n0 + arow) * DIN + koff + acol
                    : gate + (size_t)arow * DIN + koff + acol;

    uint64_t acc[4][4];
    #pragma unroll
    for (int i = 0; i < 4; i++)
        #pragma unroll
        for (int j = 0; j < 4; j++) acc[i][j] = 0ull;

    float4 av[2], bv;
    auto sts = [&](int buf) {
        #pragma unroll
        for (int p = 0; p < 2; p++) {
            As[buf][acol + 0][arow + p * 64] = av[p].x;
            As[buf][acol + 1][arow + p * 64] = av[p].y;
            As[buf][acol + 2][arow + p * 64] = av[p].z;
            As[buf][acol + 3][arow + p * 64] = av[p].w;
        }
        Bs[buf][acol + 0][arow] = bv.x;
        Bs[buf][acol + 1][arow] = bv.y;
        Bs[buf][acol + 2][arow] = bv.z;
        Bs[buf][acol + 3][arow] = bv.w;
    };

    av[0] = *(const float4*)(Ag);
    av[1] = *(const float4*)(Ag + (size_t)64 * DIN);
    bv = *(const float4*)(Bg);
    sts(0);
    __syncthreads();

    const int nk = DIN / KSPL / BK;
    for (int kt = 0; kt < nk; kt++) {
        const int cur = kt & 1;
        if (kt + 1 < nk) {
            av[0] = *(const float4*)(Ag + (kt + 1) * BK);
            av[1] = *(const float4*)(Ag + (kt + 1) * BK + (size_t)64 * DIN);
            bv = *(const float4*)(Bg + (kt + 1) * BK);
        }
        #pragma unroll
        for (int kk = 0; kk < BK; kk++) {
            uint64_t a2[4], bd[4];
            {
                ulonglong2 p0 = *(const ulonglong2*)&As[cur][kk][ty * 8];
                ulonglong2 p1 = *(const ulonglong2*)&As[cur][kk][ty * 8 + 4];
                a2[0] = p0.x; a2[1] = p0.y; a2[2] = p1.x; a2[3] = p1.y;
            }
            #pragma unroll
            for (int j = 0; j < 4; j++)
                bd[j] = dup32(Bs[cur][kk][tx * 4 + j]);
            #pragma unroll
            for (int i = 0; i < 4; i++)
                #pragma unroll
                for (int j = 0; j < 4; j++)
                    fma2(acc[i][j], a2[i], bd[j]);
        }
        if (kt + 1 < nk) {
            sts(cur ^ 1);
            __syncthreads();
        }
    }

    float* outp = g_p + (size_t)blockIdx.z * TT * N2;
    const int row0 = t0 + ty * 8;
    const int col0 = n0 + tx * 4;
    #pragma unroll
    for (int i = 0; i < 4; i++)
        #pragma unroll
        for (int j = 0; j < 4; j++) {
            float2 v = unpk(acc[i][j]);
            outp[(size_t)(row0 + 2 * i) * N2 + col0 + j] = v.x;
            outp[(size_t)(row0 + 2 * i + 1) * N2 + col0 + j] = v.y;
        }
}

// ---------------------------------------------------------------------------
__global__ void rl_kernel() {
    int idx = blockIdx.x * blockDim.x + threadIdx.x;
    if (idx >= TT * NE) return;
    int t = idx >> 3, e = idx & 7;
    const float* p0 = g_p + (size_t)t * N2 + 256 + e * 8;
    float s = 0.f;
    #pragma unroll
    for (int r = 0; r < 8; r++) {
        float gl = 0.f;
        #pragma unroll
        for (int ks = 0; ks < KSPL; ks++)
            gl += p0[(size_t)ks * TT * N2 + r];
        s += gl * gl;
    }
    g_rl[idx] = sqrtf(s);
}

__global__ void finalize_w() {
    int t = blockIdx.x * blockDim.x + threadIdx.x;
    if (t >= TT) return;
    float rl[NE];
    #pragma unroll
    for (int e = 0; e < NE; e++) rl[e] = g_rl[t * NE + e];
    int i1 = 0;
    #pragma unroll
    for (int e = 1; e < NE; e++) if (rl[e] > rl[i1]) i1 = e;
    int i2 = (i1 == 0) ? 1 : 0;
    #pragma unroll
    for (int e = 0; e < NE; e++) if (e != i1 && rl[e] > rl[i2]) i2 = e;
    float e2 = expf(rl[i2] - rl[i1]);
    float inv = 1.f / (1.f + e2);
    #pragma unroll
    for (int e = 0; e < NE; e++)
        g_w[t * NE + e] = (e == i1) ? inv : ((e == i2) ? e2 * inv : 0.f);
}

__global__ void aext_build() {
    int idx = blockIdx.x * blockDim.x + threadIdx.x;
    if (idx >= TT * (KEXT / 4)) return;
    int t = idx / (KEXT / 4);
    int k4 = idx - t * (KEXT / 4);
    float4 v;
    if (k4 < 64) {
        const float* p0 = g_p + (size_t)t * N2 + k4 * 4;
        v = *(const float4*)(p0);
        #pragma unroll
        for (int ks = 1; ks < KSPL; ks++) {
            float4 sp = *(const float4*)(p0 + (size_t)ks * TT * N2);
            v.x += sp.x; v.y += sp.y; v.z += sp.z; v.w += sp.w;
        }
        float we = g_w[t * NE + (k4 >> 3)];
        v.x *= we; v.y *= we; v.z *= we; v.w *= we;
    } else if (k4 < 66) {
        const float* wp = g_w + t * NE + (k4 - 64) * 4;
        v = make_float4(wp[0], wp[1], wp[2], wp[3]);
    } else {
        v = make_float4(0.f, 0.f, 0.f, 0.f);
    }
    *(float4*)(g_aext + (size_t)t * KEXT + k4 * 4) = v;
}

// ---------------------------------------------------------------------------
// FFMA2 shared-path GEMM, cols [0, CSPL) (R10/R12-proven structure)
// ---------------------------------------------------------------------------
#define LA 132
#define LBR 144

__global__ __launch_bounds__(256, 2) void seg0_gemm(const float* __restrict__ X,
                                                    const float* __restrict__ W,
                                                    const float* __restrict__ Bias,
                                                    float* __restrict__ C) {
    constexpr int BK = 16;
    __shared__ __align__(16) float As[2][BK][LA];
    __shared__ __align__(16) float Bs[2][BK][LBR];
    const int tid = threadIdx.x;
    const int tx = tid & 15, ty = tid >> 4;
    const int arow = tid >> 2;
    const int acol = (tid & 3) * 4;
    const int bslot = ((arow >> 3) * 9) + (arow & 7);

    uint64_t acc[4][8];
    #pragma unroll
    for (int i = 0; i < 4; i++)
        #pragma unroll
        for (int j = 0; j < 8; j++) acc[i][j] = 0ull;

    float4 av[2], bv[2];
    auto sts = [&](int buf) {
        #pragma unroll
        for (int p = 0; p < 2; p++) {
            As[buf][acol + 0][arow + p * 64] = av[p].x;
            As[buf][acol + 1][arow + p * 64] = av[p].y;
            As[buf][acol + 2][arow + p * 64] = av[p].z;
            As[buf][acol + 3][arow + p * 64] = av[p].w;
            Bs[buf][acol + 0][bslot + p * 72] = bv[p].x;
            Bs[buf][acol + 1][bslot + p * 72] = bv[p].y;
            Bs[buf][acol + 2][bslot + p * 72] = bv[p].z;
            Bs[buf][acol + 3][bslot + p * 72] = bv[p].w;
        }
    };

    const float* Ag = X + (size_t)(blockIdx.y * 128 + arow) * DIN + acol;
    const float* Bg = W + (size_t)(blockIdx.x * 128 + arow) * DIN + acol;

    av[0] = *(const float4*)(Ag);
    av[1] = *(const float4*)(Ag + (size_t)64 * DIN);
    bv[0] = *(const float4*)(Bg);
    bv[1] = *(const float4*)(Bg + (size_t)64 * DIN);
    sts(0);
    __syncthreads();

    const int nk = DIN / BK;
    for (int kt = 0; kt < nk; kt++) {
        const int cur = kt & 1;
        if (kt + 1 < nk) {
            av[0] = *(const float4*)(Ag + (kt + 1) * BK);
            av[1] = *(const float4*)(Ag + (kt + 1) * BK + (size_t)64 * DIN);
            bv[0] = *(const float4*)(Bg + (kt + 1) * BK);
            bv[1] = *(const float4*)(Bg + (kt + 1) * BK + (size_t)64 * DIN);
        }
        #pragma unroll
        for (int kk = 0; kk < BK; kk++) {
            uint64_t a2[4], bd[8];
            {
                ulonglong2 p0 = *(const ulonglong2*)&As[cur][kk][ty * 8];
                ulonglong2 p1 = *(const ulonglong2*)&As[cur][kk][ty * 8 + 4];
                a2[0] = p0.x; a2[1] = p0.y; a2[2] = p1.x; a2[3] = p1.y;
            }
            #pragma unroll
            for (int j = 0; j < 8; j++)
                bd[j] = dup32(Bs[cur][kk][tx * 9 + j]);
            #pragma unroll
            for (int i = 0; i < 4; i++)
                #pragma unroll
                for (int j = 0; j < 8; j++)
                    fma2(acc[i][j], a2[i], bd[j]);
        }
        if (kt + 1 < nk) {
            sts(cur ^ 1);
            __syncthreads();
        }
    }

    const int row0 = blockIdx.y * 128 + ty * 8;
    const int col0 = blockIdx.x * 128 + tx * 8;
    #pragma unroll
    for (int i = 0; i < 4; i++)
        #pragma unroll
        for (int j = 0; j < 8; j++) {
            float2 v = unpk(acc[i][j]);
            float b = Bias[col0 + j];
            C[(size_t)(row0 + 2 * i) * DOUT + col0 + j] = v.x + b;
            C[(size_t)(row0 + 2 * i + 1) * DOUT + col0 + j] = v.y + b;
        }
}

// ---------------------------------------------------------------------------
// FFMA2 expert add-GEMM: out += aext @ bext^T (K=272), cols [coff + 128*bx).
// ---------------------------------------------------------------------------
__global__ __launch_bounds__(256, 2) void exp_gemm(float* __restrict__ C, int coff) {
    constexpr int BK = 16;
    __shared__ __align__(16) float As[2][BK][LA];
    __shared__ __align__(16) float Bs[2][BK][LBR];
    const int tid = threadIdx.x;
    const int tx = tid & 15, ty = tid >> 4;
    const int arow = tid >> 2;
    const int acol = (tid & 3) * 4;
    const int bslot = ((arow >> 3) * 9) + (arow & 7);
    const int nb0 = coff + blockIdx.x * 128;

    uint64_t acc[4][8];
    #pragma unroll
    for (int i = 0; i < 4; i++)
        #pragma unroll
        for (int j = 0; j < 8; j++) acc[i][j] = 0ull;

    float4 av[2], bv[2];
    auto sts = [&](int buf) {
        #pragma unroll
        for (int p = 0; p < 2; p++) {
            As[buf][acol + 0][arow + p * 64] = av[p].x;
            As[buf][acol + 1][arow + p * 64] = av[p].y;
            As[buf][acol + 2][arow + p * 64] = av[p].z;
            As[buf][acol + 3][arow + p * 64] = av[p].w;
            Bs[buf][acol + 0][bslot + p * 72] = bv[p].x;
            Bs[buf][acol + 1][bslot + p * 72] = bv[p].y;
            Bs[buf][acol + 2][bslot + p * 72] = bv[p].z;
            Bs[buf][acol + 3][bslot + p * 72] = bv[p].w;
        }
    };

    const float* Ag = g_aext + (size_t)(blockIdx.y * 128 + arow) * KEXT + acol;
    const float* Bg = g_bext + (size_t)(nb0 + arow) * KEXT + acol;

    av[0] = *(const float4*)(Ag);
    av[1] = *(const float4*)(Ag + (size_t)64 * KEXT);
    bv[0] = *(const float4*)(Bg);
    bv[1] = *(const float4*)(Bg + (size_t)64 * KEXT);
    sts(0);
    __syncthreads();

    const int nk = KEXT / BK;   // 17
    for (int kt = 0; kt < nk; kt++) {
        const int cur = kt & 1;
        if (kt + 1 < nk) {
            av[0] = *(const float4*)(Ag + (kt + 1) * BK);
            av[1] = *(const float4*)(Ag + (kt + 1) * BK + (size_t)64 * KEXT);
            bv[0] = *(const float4*)(Bg + (kt + 1) * BK);
            bv[1] = *(const float4*)(Bg + (kt + 1) * BK + (size_t)64 * KEXT);
        }
        #pragma unroll
        for (int kk = 0; kk < BK; kk++) {
            uint64_t a2[4], bd[8];
            {
                ulonglong2 p0 = *(const ulonglong2*)&As[cur][kk][ty * 8];
                ulonglong2 p1 = *(const ulonglong2*)&As[cur][kk][ty * 8 + 4];
                a2[0] = p0.x; a2[1] = p0.y; a2[2] = p1.x; a2[3] = p1.y;
            }
            #pragma unroll
            for (int j = 0; j < 8; j++)
                bd[j] = dup32(Bs[cur][kk][tx * 9 + j]);
            #pragma unroll
            for (int i = 0; i < 4; i++)
                #pragma unroll
                for (int j = 0; j < 8; j++)
                    fma2(acc[i][j], a2[i], bd[j]);
        }
        if (kt + 1 < nk) {
            sts(cur ^ 1);
            __syncthreads();
        }
    }

    const int row0 = blockIdx.y * 128 + ty * 8;
    const int col0 = nb0 + tx * 8;
    #pragma unroll
    for (int i = 0; i < 4; i++)
        #pragma unroll
        for (int j = 0; j < 8; j++) {
            float2 v = unpk(acc[i][j]);
            C[(size_t)(row0 + 2 * i) * DOUT + col0 + j] += v.x;
            C[(size_t)(row0 + 2 * i + 1) * DOUT + col0 + j] += v.y;
        }
}

// ---------------------------------------------------------------------------
// tf32 mma.sync GEMM (R6/R13-proven, cvt in loop): C = A B^T + bias.
// ---------------------------------------------------------------------------
#define TSS 36
#define TSTAGE ((256 + 128) * TSS)
#define TSMEM (2 * TSTAGE * 4)

__global__ __launch_bounds__(256, 1)
void ttgemm(const float* __restrict__ A, const float* __restrict__ B,
            int lda, int ldb, int nch,
            float* __restrict__ C, int ldc, const float* __restrict__ bias) {
    extern __shared__ __align__(16) float sm[];
    const int tid = threadIdx.x;
    const int m0 = blockIdx.y * 256, n0 = blockIdx.x * 128;

    auto load_stage = [&](int c, int buf) {
        const int kc0 = c * 32;
        float* sA = sm + buf * TSTAGE;
        float* sB = sA + 256 * TSS;
        #pragma unroll
        for (int i = 0; i < 8; i++) {
            int idx = tid + i * 256;
            int m = idx >> 3, kc = (idx & 7) * 4;
            cpa16(smem_u32(sA + m * TSS + kc), A + (size_t)(m0 + m) * lda + kc0 + kc);
        }
        #pragma unroll
        for (int i = 0; i < 4; i++) {
            int idx = tid + i * 256;
            int nn = idx >> 3, kc = (idx & 7) * 4;
            cpa16(smem_u32(sB + nn * TSS + kc), B + (size_t)(n0 + nn) * ldb + kc0 + kc);
        }
        asm volatile("cp.async.commit_group;" ::: "memory");
    };

    float acc[4][8][4];
    #pragma unroll
    for (int i = 0; i < 4; i++)
        #pragma unroll
        for (int j = 0; j < 8; j++)
            #pragma unroll
            for (int q = 0; q < 4; q++) acc[i][j][q] = 0.f;

    const int warp = tid >> 5, lane = tid & 31;
    const int qr = lane >> 2, qc = lane & 3;
    const int wm = warp >> 1, wn = warp & 1;

    load_stage(0, 0);
    load_stage(1, 1);

    #pragma unroll 1
    for (int c = 0; c < nch; c++) {
        const int buf = c & 1;
        if (c + 1 < nch) asm volatile("cp.async.wait_group 1;" ::: "memory");
        else             asm volatile("cp.async.wait_group 0;" ::: "memory");
        __syncthreads();
        const float* sA = sm + buf * TSTAGE + (wm * 64 + qr) * TSS + qc;
        const float* sB = sm + buf * TSTAGE + 256 * TSS + (wn * 64 + qr) * TSS + qc;

        #pragma unroll
        for (int kk = 0; kk < 4; kk++) {
            uint32_t af[4][4], bf[8][2];
            #pragma unroll
            for (int mt = 0; mt < 4; mt++) {
                const float* p = sA + mt * 16 * TSS + kk * 8;
                af[mt][0] = f2tf32(p[0]);
                af[mt][1] = f2tf32(p[8 * TSS]);
                af[mt][2] = f2tf32(p[4]);
                af[mt][3] = f2tf32(p[8 * TSS + 4]);
            }
            #pragma unroll
            for (int nt = 0; nt < 8; nt++) {
                const float* p = sB + nt * 8 * TSS + kk * 8;
                bf[nt][0] = f2tf32(p[0]);
                bf[nt][1] = f2tf32(p[4]);
            }
            #pragma unroll
            for (int mt = 0; mt < 4; mt++)
                #pragma unroll
                for (int nt = 0; nt < 8; nt++)
                    mma8(acc[mt][nt], af[mt], bf[nt]);
        }
        __syncthreads();
        if (c + 2 < nch) load_stage(c + 2, buf);
    }

    const int rbase = m0 + wm * 64;
    const int cbase = n0 + wn * 64;
    #pragma unroll
    for (int mt = 0; mt < 4; mt++) {
        #pragma unroll
        for (int nt = 0; nt < 8; nt++) {
            const int r = rbase + mt * 16 + qr;
            const int col = cbase + nt * 8 + qc * 2;
            float bx = bias[col], by = bias[col + 1];
            float2 v0 = make_float2(acc[mt][nt][0] + bx, acc[mt][nt][1] + by);
            float2 v1 = make_float2(acc[mt][nt][2] + bx, acc[mt][nt][3] + by);
            *(float2*)(C + (size_t)r * ldc + col) = v0;
            *(float2*)(C + (size_t)(r + 8) * ldc + col) = v1;
        }
    }
}

// ---------------------------------------------------------------------------
extern "C" void kernel_launch(void* const* d_in, const int* in_sizes, int n_in,
                              void* d_out, int out_size) {
    const float* x    = (const float*)d_in[0];
    const float* gate = (const float*)d_in[1];
    const float* shw  = (const float*)d_in[2];
    const float* shb  = (const float*)d_in[3];
    const float* u    = (const float*)d_in[4];
    const float* svh  = (const float*)d_in[5];
    const float* eb   = (const float*)d_in[6];
    float* out = (float*)d_out;

    static cudaStream_t s1, s2;
    static cudaEvent_t e0, e1, e2;
    static int once = 0;
    if (!once) {
        cudaStreamCreateWithFlags(&s1, cudaStreamNonBlocking);
        cudaStreamCreateWithFlags(&s2, cudaStreamNonBlocking);
        cudaEventCreateWithFlags(&e0, cudaEventDisableTiming);
        cudaEventCreateWithFlags(&e1, cudaEventDisableTiming);
        cudaEventCreateWithFlags(&e2, cudaEventDisableTiming);
        cudaFuncSetAttribute(ttgemm, cudaFuncAttributeMaxDynamicSharedMemorySize, TSMEM);
        cudaFuncSetAttribute(seg0_gemm,
                             cudaFuncAttributePreferredSharedMemoryCarveout, 100);
        cudaFuncSetAttribute(exp_gemm,
                             cudaFuncAttributePreferredSharedMemoryCarveout, 100);
        once = 1;
    }

    // fork
    cudaEventRecord(e0, 0);
    cudaStreamWaitEvent(s1, e0, 0);
    cudaStreamWaitEvent(s2, e0, 0);

    // s1: small chain -> aext
    bext_kernel<<<(DOUT * KEXT + 255) / 256, 256, 0, s1>>>(u, eb);
    skgemm<<<dim3(N2 / 64, TT / 128, KSPL), 256, 0, s1>>>(x, svh, gate);
    rl_kernel<<<(TT * NE + 255) / 256, 256, 0, s1>>>();
    finalize_w<<<(TT + 255) / 256, 256, 0, s1>>>();
    aext_build<<<(TT * (KEXT / 4) + 255) / 256, 256, 0, s1>>>();
    cudaEventRecord(e1, s1);

    // s2: tf32 mma half (cols [CSPL,4096)) then its expert add
    ttgemm<<<dim3((DOUT - CSPL) / 128, TT / 256), 256, TSMEM, s2>>>(
        x, shw + (size_t)CSPL * DIN, DIN, DIN, DIN / 32,
        out + CSPL, DOUT, shb + CSPL);
    cudaStreamWaitEvent(s2, e1, 0);
    exp_gemm<<<dim3((DOUT - CSPL) / 128, TT / 128), 256, 0, s2>>>(out, CSPL);
    cudaEventRecord(e2, s2);

    // default: FFMA2 half (cols [0,CSPL)) then its expert add
    seg0_gemm<<<dim3(CSPL / 128, TT / 128), 256>>>(x, shw, shb, out);
    cudaStreamWaitEvent(0, e1, 0);
    exp_gemm<<<dim3(CSPL / 128, TT / 128), 256>>>(out, 0);

    // join s2 back to origin
    cudaStreamWaitEvent(0, e2, 0);
}

// round 16
// speedup vs baseline: 6.8712x; 1.0479x over previous
#include <cuda_runtime.h>
#include <cstdint>
#include <math.h>

// Problem constants
#define TT    4096
#define DIN   4096
#define DOUT  4096
#define NE    8
#define N2    320    // [svh(256) | gate(64)]
#define KEXT  272    // 256 + 8 (w->bias) + 8 zero pad -> 17 chunks of 16
#define KSPL  4
#define CSPL  2048   // cols [0,CSPL) FFMA2, [CSPL,4096) tf32 mma

// Scratch (device globals; allocation is forbidden)
__device__ float g_p[KSPL * TT * N2];
__device__ float g_rl[TT * NE];
__device__ float g_w[TT * NE];
__device__ float g_aext[TT * KEXT];
__device__ float g_bext[DOUT * KEXT];

// ---------------- f32x2 packed-FMA helpers ----------
__device__ __forceinline__ void fma2(uint64_t& d, uint64_t a, uint64_t b) {
    asm("fma.rn.f32x2 %0, %1, %2, %0;" : "+l"(d) : "l"(a), "l"(b));
}
__device__ __forceinline__ uint64_t dup32(float v) {
    uint64_t r;
    asm("mov.b64 %0, {%1, %1};" : "=l"(r) : "f"(v));
    return r;
}
__device__ __forceinline__ float2 unpk(uint64_t v) {
    float2 r;
    asm("mov.b64 {%0, %1}, %2;" : "=f"(r.x), "=f"(r.y) : "l"(v));
    return r;
}
// ---------------- tf32 mma helpers ----------
__device__ __forceinline__ uint32_t smem_u32(const void* p) {
    uint32_t a;
    asm("{ .reg .u64 t; cvta.to.shared.u64 t, %1; cvt.u32.u64 %0, t; }" : "=r"(a) : "l"(p));
    return a;
}
__device__ __forceinline__ void cpa16(uint32_t dst, const void* src) {
    asm volatile("cp.async.cg.shared.global [%0], [%1], 16;" :: "r"(dst), "l"(src));
}
__device__ __forceinline__ uint32_t f2tf32(float f) {
    uint32_t r;
    asm("cvt.rna.tf32.f32 %0, %1;" : "=r"(r) : "f"(f));
    return r;
}
__device__ __forceinline__ void mma8(float* c, const uint32_t* a, const uint32_t* b) {
    asm volatile(
        "mma.sync.aligned.m16n8k8.row.col.f32.tf32.tf32.f32 "
        "{%0,%1,%2,%3}, {%4,%5,%6,%7}, {%8,%9}, {%0,%1,%2,%3};"
        : "+f"(c[0]), "+f"(c[1]), "+f"(c[2]), "+f"(c[3])
        : "r"(a[0]), "r"(a[1]), "r"(a[2]), "r"(a[3]), "r"(b[0]), "r"(b[1]));
}

// ---------------------------------------------------------------------------
__global__ void bext_kernel(const float* __restrict__ u, const float* __restrict__ eb) {
    int idx = blockIdx.x * blockDim.x + threadIdx.x;
    if (idx >= DOUT * KEXT) return;
    int n = idx / KEXT;
    int k = idx - n * KEXT;
    float v = 0.f;
    if (k < 256) {
        int e = k >> 5, r = k & 31;
        v = u[(e * DOUT + n) * 32 + r];
    } else if (k < 264) {
        v = eb[(k - 256) * DOUT + n];
    }
    g_bext[idx] = v;
}

// ---------------------------------------------------------------------------
// Split-K fused small GEMM (R12-proven verbatim)
// ---------------------------------------------------------------------------
__global__ __launch_bounds__(256) void skgemm(const float* __restrict__ A,
                                              const float* __restrict__ svh,
                                              const float* __restrict__ gate) {
    constexpr int BK = 16;
    constexpr int LAs = 132, LBs = 68;
    __shared__ float As[2][BK][LAs];
    __shared__ float Bs[2][BK][LBs];
    const int tid = threadIdx.x;
    const int tx = tid & 15, ty = tid >> 4;
    const int arow = tid >> 2;
    const int acol = (tid & 3) * 4;
    const int n0 = blockIdx.x * 64;
    const int t0 = blockIdx.y * 128;
    const int koff = blockIdx.z * (DIN / KSPL);

    const float* Ag = A + (size_t)(t0 + arow) * DIN + koff + acol;
    const float* Bg = (blockIdx.x < 4)
                    ? svh + (size_t)(n0 + arow) * DIN + koff + acol
                    : gate + (size_t)arow * DIN + koff + acol;

    uint64_t acc[4][4];
    #pragma unroll
    for (int i = 0; i < 4; i++)
        #pragma unroll
        for (int j = 0; j < 4; j++) acc[i][j] = 0ull;

    float4 av[2], bv;
    auto sts = [&](int buf) {
        #pragma unroll
        for (int p = 0; p < 2; p++) {
            As[buf][acol + 0][arow + p * 64] = av[p].x;
            As[buf][acol + 1][arow + p * 64] = av[p].y;
            As[buf][acol + 2][arow + p * 64] = av[p].z;
            As[buf][acol + 3][arow + p * 64] = av[p].w;
        }
        Bs[buf][acol + 0][arow] = bv.x;
        Bs[buf][acol + 1][arow] = bv.y;
        Bs[buf][acol + 2][arow] = bv.z;
        Bs[buf][acol + 3][arow] = bv.w;
    };

    av[0] = *(const float4*)(Ag);
    av[1] = *(const float4*)(Ag + (size_t)64 * DIN);
    bv = *(const float4*)(Bg);
    sts(0);
    __syncthreads();

    const int nk = DIN / KSPL / BK;
    for (int kt = 0; kt < nk; kt++) {
        const int cur = kt & 1;
        if (kt + 1 < nk) {
            av[0] = *(const float4*)(Ag + (kt + 1) * BK);
            av[1] = *(const float4*)(Ag + (kt + 1) * BK + (size_t)64 * DIN);
            bv = *(const float4*)(Bg + (kt + 1) * BK);
        }
        #pragma unroll
        for (int kk = 0; kk < BK; kk++) {
            uint64_t a2[4], bd[4];
            {
                ulonglong2 p0 = *(const ulonglong2*)&As[cur][kk][ty * 8];
                ulonglong2 p1 = *(const ulonglong2*)&As[cur][kk][ty * 8 + 4];
                a2[0] = p0.x; a2[1] = p0.y; a2[2] = p1.x; a2[3] = p1.y;
            }
            #pragma unroll
            for (int j = 0; j < 4; j++)
                bd[j] = dup32(Bs[cur][kk][tx * 4 + j]);
            #pragma unroll
            for (int i = 0; i < 4; i++)
                #pragma unroll
                for (int j = 0; j < 4; j++)
                    fma2(acc[i][j], a2[i], bd[j]);
        }
        if (kt + 1 < nk) {
            sts(cur ^ 1);
            __syncthreads();
        }
    }

    float* outp = g_p + (size_t)blockIdx.z * TT * N2;
    const int row0 = t0 + ty * 8;
    const int col0 = n0 + tx * 4;
    #pragma unroll
    for (int i = 0; i < 4; i++)
        #pragma unroll
        for (int j = 0; j < 4; j++) {
            float2 v = unpk(acc[i][j]);
            outp[(size_t)(row0 + 2 * i) * N2 + col0 + j] = v.x;
            outp[(size_t)(row0 + 2 * i + 1) * N2 + col0 + j] = v.y;
        }
}

// ---------------------------------------------------------------------------
__global__ void rl_kernel() {
    int idx = blockIdx.x * blockDim.x + threadIdx.x;
    if (idx >= TT * NE) return;
    int t = idx >> 3, e = idx & 7;
    const float* p0 = g_p + (size_t)t * N2 + 256 + e * 8;
    float s = 0.f;
    #pragma unroll
    for (int r = 0; r < 8; r++) {
        float gl = 0.f;
        #pragma unroll
        for (int ks = 0; ks < KSPL; ks++)
            gl += p0[(size_t)ks * TT * N2 + r];
        s += gl * gl;
    }
    g_rl[idx] = sqrtf(s);
}

__global__ void finalize_w() {
    int t = blockIdx.x * blockDim.x + threadIdx.x;
    if (t >= TT) return;
    float rl[NE];
    #pragma unroll
    for (int e = 0; e < NE; e++) rl[e] = g_rl[t * NE + e];
    int i1 = 0;
    #pragma unroll
    for (int e = 1; e < NE; e++) if (rl[e] > rl[i1]) i1 = e;
    int i2 = (i1 == 0) ? 1 : 0;
    #pragma unroll
    for (int e = 0; e < NE; e++) if (e != i1 && rl[e] > rl[i2]) i2 = e;
    float e2 = expf(rl[i2] - rl[i1]);
    float inv = 1.f / (1.f + e2);
    #pragma unroll
    for (int e = 0; e < NE; e++)
        g_w[t * NE + e] = (e == i1) ? inv : ((e == i2) ? e2 * inv : 0.f);
}

__global__ void aext_build() {
    int idx = blockIdx.x * blockDim.x + threadIdx.x;
    if (idx >= TT * (KEXT / 4)) return;
    int t = idx / (KEXT / 4);
    int k4 = idx - t * (KEXT / 4);
    float4 v;
    if (k4 < 64) {
        const float* p0 = g_p + (size_t)t * N2 + k4 * 4;
        v = *(const float4*)(p0);
        #pragma unroll
        for (int ks = 1; ks < KSPL; ks++) {
            float4 sp = *(const float4*)(p0 + (size_t)ks * TT * N2);
            v.x += sp.x; v.y += sp.y; v.z += sp.z; v.w += sp.w;
        }
        float we = g_w[t * NE + (k4 >> 3)];
        v.x *= we; v.y *= we; v.z *= we; v.w *= we;
    } else if (k4 < 66) {
        const float* wp = g_w + t * NE + (k4 - 64) * 4;
        v = make_float4(wp[0], wp[1], wp[2], wp[3]);
    } else {
        v = make_float4(0.f, 0.f, 0.f, 0.f);
    }
    *(float4*)(g_aext + (size_t)t * KEXT + k4 * 4) = v;
}

// ---------------------------------------------------------------------------
// FFMA2 shared-path GEMM, cols [0, CSPL) (R10/R12-proven structure)
// ---------------------------------------------------------------------------
#define LA 132
#define LBR 144

__global__ __launch_bounds__(256, 2) void seg0_gemm(const float* __restrict__ X,
                                                    const float* __restrict__ W,
                                                    const float* __restrict__ Bias,
                                                    float* __restrict__ C) {
    constexpr int BK = 16;
    __shared__ __align__(16) float As[2][BK][LA];
    __shared__ __align__(16) float Bs[2][BK][LBR];
    const int tid = threadIdx.x;
    const int tx = tid & 15, ty = tid >> 4;
    const int arow = tid >> 2;
    const int acol = (tid & 3) * 4;
    const int bslot = ((arow >> 3) * 9) + (arow & 7);

    uint64_t acc[4][8];
    #pragma unroll
    for (int i = 0; i < 4; i++)
        #pragma unroll
        for (int j = 0; j < 8; j++) acc[i][j] = 0ull;

    float4 av[2], bv[2];
    auto sts = [&](int buf) {
        #pragma unroll
        for (int p = 0; p < 2; p++) {
            As[buf][acol + 0][arow + p * 64] = av[p].x;
            As[buf][acol + 1][arow + p * 64] = av[p].y;
            As[buf][acol + 2][arow + p * 64] = av[p].z;
            As[buf][acol + 3][arow + p * 64] = av[p].w;
            Bs[buf][acol + 0][bslot + p * 72] = bv[p].x;
            Bs[buf][acol + 1][bslot + p * 72] = bv[p].y;
            Bs[buf][acol + 2][bslot + p * 72] = bv[p].z;
            Bs[buf][acol + 3][bslot + p * 72] = bv[p].w;
        }
    };

    const float* Ag = X + (size_t)(blockIdx.y * 128 + arow) * DIN + acol;
    const float* Bg = W + (size_t)(blockIdx.x * 128 + arow) * DIN + acol;

    av[0] = *(const float4*)(Ag);
    av[1] = *(const float4*)(Ag + (size_t)64 * DIN);
    bv[0] = *(const float4*)(Bg);
    bv[1] = *(const float4*)(Bg + (size_t)64 * DIN);
    sts(0);
    __syncthreads();

    const int nk = DIN / BK;
    for (int kt = 0; kt < nk; kt++) {
        const int cur = kt & 1;
        if (kt + 1 < nk) {
            av[0] = *(const float4*)(Ag + (kt + 1) * BK);
            av[1] = *(const float4*)(Ag + (kt + 1) * BK + (size_t)64 * DIN);
            bv[0] = *(const float4*)(Bg + (kt + 1) * BK);
            bv[1] = *(const float4*)(Bg + (kt + 1) * BK + (size_t)64 * DIN);
        }
        #pragma unroll
        for (int kk = 0; kk < BK; kk++) {
            uint64_t a2[4], bd[8];
            {
                ulonglong2 p0 = *(const ulonglong2*)&As[cur][kk][ty * 8];
                ulonglong2 p1 = *(const ulonglong2*)&As[cur][kk][ty * 8 + 4];
                a2[0] = p0.x; a2[1] = p0.y; a2[2] = p1.x; a2[3] = p1.y;
            }
            #pragma unroll
            for (int j = 0; j < 8; j++)
                bd[j] = dup32(Bs[cur][kk][tx * 9 + j]);
            #pragma unroll
            for (int i = 0; i < 4; i++)
                #pragma unroll
                for (int j = 0; j < 8; j++)
                    fma2(acc[i][j], a2[i], bd[j]);
        }
        if (kt + 1 < nk) {
            sts(cur ^ 1);
            __syncthreads();
        }
    }

    const int row0 = blockIdx.y * 128 + ty * 8;
    const int col0 = blockIdx.x * 128 + tx * 8;
    #pragma unroll
    for (int i = 0; i < 4; i++)
        #pragma unroll
        for (int j = 0; j < 8; j++) {
            float2 v = unpk(acc[i][j]);
            float b = Bias[col0 + j];
            C[(size_t)(row0 + 2 * i) * DOUT + col0 + j] = v.x + b;
            C[(size_t)(row0 + 2 * i + 1) * DOUT + col0 + j] = v.y + b;
        }
}

// ---------------------------------------------------------------------------
// FFMA2 expert add-GEMM: out += aext @ bext^T (K=272), cols [coff + 128*bx).
// ---------------------------------------------------------------------------
__global__ __launch_bounds__(256, 2) void exp_gemm(float* __restrict__ C, int coff) {
    constexpr int BK = 16;
    __shared__ __align__(16) float As[2][BK][LA];
    __shared__ __align__(16) float Bs[2][BK][LBR];
    const int tid = threadIdx.x;
    const int tx = tid & 15, ty = tid >> 4;
    const int arow = tid >> 2;
    const int acol = (tid & 3) * 4;
    const int bslot = ((arow >> 3) * 9) + (arow & 7);
    const int nb0 = coff + blockIdx.x * 128;

    uint64_t acc[4][8];
    #pragma unroll
    for (int i = 0; i < 4; i++)
        #pragma unroll
        for (int j = 0; j < 8; j++) acc[i][j] = 0ull;

    float4 av[2], bv[2];
    auto sts = [&](int buf) {
        #pragma unroll
        for (int p = 0; p < 2; p++) {
            As[buf][acol + 0][arow + p * 64] = av[p].x;
            As[buf][acol + 1][arow + p * 64] = av[p].y;
            As[buf][acol + 2][arow + p * 64] = av[p].z;
            As[buf][acol + 3][arow + p * 64] = av[p].w;
            Bs[buf][acol + 0][bslot + p * 72] = bv[p].x;
            Bs[buf][acol + 1][bslot + p * 72] = bv[p].y;
            Bs[buf][acol + 2][bslot + p * 72] = bv[p].z;
            Bs[buf][acol + 3][bslot + p * 72] = bv[p].w;
        }
    };

    const float* Ag = g_aext + (size_t)(blockIdx.y * 128 + arow) * KEXT + acol;
    const float* Bg = g_bext + (size_t)(nb0 + arow) * KEXT + acol;

    av[0] = *(const float4*)(Ag);
    av[1] = *(const float4*)(Ag + (size_t)64 * KEXT);
    bv[0] = *(const float4*)(Bg);
    bv[1] = *(const float4*)(Bg + (size_t)64 * KEXT);
    sts(0);
    __syncthreads();

    const int nk = KEXT / BK;   // 17
    for (int kt = 0; kt < nk; kt++) {
        const int cur = kt & 1;
        if (kt + 1 < nk) {
            av[0] = *(const float4*)(Ag + (kt + 1) * BK);
            av[1] = *(const float4*)(Ag + (kt + 1) * BK + (size_t)64 * KEXT);
            bv[0] = *(const float4*)(Bg + (kt + 1) * BK);
            bv[1] = *(const float4*)(Bg + (kt + 1) * BK + (size_t)64 * KEXT);
        }
        #pragma unroll
        for (int kk = 0; kk < BK; kk++) {
            uint64_t a2[4], bd[8];
            {
                ulonglong2 p0 = *(const ulonglong2*)&As[cur][kk][ty * 8];
                ulonglong2 p1 = *(const ulonglong2*)&As[cur][kk][ty * 8 + 4];
                a2[0] = p0.x; a2[1] = p0.y; a2[2] = p1.x; a2[3] = p1.y;
            }
            #pragma unroll
            for (int j = 0; j < 8; j++)
                bd[j] = dup32(Bs[cur][kk][tx * 9 + j]);
            #pragma unroll
            for (int i = 0; i < 4; i++)
                #pragma unroll
                for (int j = 0; j < 8; j++)
                    fma2(acc[i][j], a2[i], bd[j]);
        }
        if (kt + 1 < nk) {
            sts(cur ^ 1);
            __syncthreads();
        }
    }

    const int row0 = blockIdx.y * 128 + ty * 8;
    const int col0 = nb0 + tx * 8;
    #pragma unroll
    for (int i = 0; i < 4; i++)
        #pragma unroll
        for (int j = 0; j < 8; j++) {
            float2 v = unpk(acc[i][j]);
            C[(size_t)(row0 + 2 * i) * DOUT + col0 + j] += v.x;
            C[(size_t)(row0 + 2 * i + 1) * DOUT + col0 + j] += v.y;
        }
}

// ---------------------------------------------------------------------------
// tf32 mma.sync GEMM, R16: 3-stage cp.async pipeline (load issued 2 chunks
// ahead, BEFORE the current compute — true prefetch distance of one full
// compute iteration). cvt in loop (R13-proven math).
// ---------------------------------------------------------------------------
#define TSS 36
#define TSTAGE ((256 + 128) * TSS)
#define TSMEM (3 * TSTAGE * 4)

__global__ __launch_bounds__(256, 1)
void ttgemm(const float* __restrict__ A, const float* __restrict__ B,
            int lda, int ldb, int nch,
            float* __restrict__ C, int ldc, const float* __restrict__ bias) {
    extern __shared__ __align__(16) float sm[];
    const int tid = threadIdx.x;
    const int m0 = blockIdx.y * 256, n0 = blockIdx.x * 128;

    auto load_stage = [&](int c, int buf) {
        const int kc0 = c * 32;
        float* sA = sm + buf * TSTAGE;
        float* sB = sA + 256 * TSS;
        #pragma unroll
        for (int i = 0; i < 8; i++) {
            int idx = tid + i * 256;
            int m = idx >> 3, kc = (idx & 7) * 4;
            cpa16(smem_u32(sA + m * TSS + kc), A + (size_t)(m0 + m) * lda + kc0 + kc);
        }
        #pragma unroll
        for (int i = 0; i < 4; i++) {
            int idx = tid + i * 256;
            int nn = idx >> 3, kc = (idx & 7) * 4;
            cpa16(smem_u32(sB + nn * TSS + kc), B + (size_t)(n0 + nn) * ldb + kc0 + kc);
        }
        asm volatile("cp.async.commit_group;" ::: "memory");
    };

    float acc[4][8][4];
    #pragma unroll
    for (int i = 0; i < 4; i++)
        #pragma unroll
        for (int j = 0; j < 8; j++)
            #pragma unroll
            for (int q = 0; q < 4; q++) acc[i][j][q] = 0.f;

    const int warp = tid >> 5, lane = tid & 31;
    const int qr = lane >> 2, qc = lane & 3;
    const int wm = warp >> 1, wn = warp & 1;

    load_stage(0, 0);
    load_stage(1, 1);

    #pragma unroll 1
    for (int c = 0; c < nch; c++) {
        const int buf = c % 3;
        if (c + 1 < nch) asm volatile("cp.async.wait_group 1;" ::: "memory");
        else             asm volatile("cp.async.wait_group 0;" ::: "memory");
        __syncthreads();
        // issue the c+2 load BEFORE computing c: its buffer was last read in
        // compute c-1, which every thread has passed (the sync above).
        if (c + 2 < nch) load_stage(c + 2, (c + 2) % 3);

        const float* sA = sm + buf * TSTAGE + (wm * 64 + qr) * TSS + qc;
        const float* sB = sm + buf * TSTAGE + 256 * TSS + (wn * 64 + qr) * TSS + qc;

        #pragma unroll
        for (int kk = 0; kk < 4; kk++) {
            uint32_t af[4][4], bf[8][2];
            #pragma unroll
            for (int mt = 0; mt < 4; mt++) {
                const float* p = sA + mt * 16 * TSS + kk * 8;
                af[mt][0] = f2tf32(p[0]);
                af[mt][1] = f2tf32(p[8 * TSS]);
                af[mt][2] = f2tf32(p[4]);
                af[mt][3] = f2tf32(p[8 * TSS + 4]);
            }
            #pragma unroll
            for (int nt = 0; nt < 8; nt++) {
                const float* p = sB + nt * 8 * TSS + kk * 8;
                bf[nt][0] = f2tf32(p[0]);
                bf[nt][1] = f2tf32(p[4]);
            }
            #pragma unroll
            for (int mt = 0; mt < 4; mt++)
                #pragma unroll
                for (int nt = 0; nt < 8; nt++)
                    mma8(acc[mt][nt], af[mt], bf[nt]);
        }
    }

    const int rbase = m0 + wm * 64;
    const int cbase = n0 + wn * 64;
    #pragma unroll
    for (int mt = 0; mt < 4; mt++) {
        #pragma unroll
        for (int nt = 0; nt < 8; nt++) {
            const int r = rbase + mt * 16 + qr;
            const int col = cbase + nt * 8 + qc * 2;
            float bx = bias[col], by = bias[col + 1];
            float2 v0 = make_float2(acc[mt][nt][0] + bx, acc[mt][nt][1] + by);
            float2 v1 = make_float2(acc[mt][nt][2] + bx, acc[mt][nt][3] + by);
            *(float2*)(C + (size_t)r * ldc + col) = v0;
            *(float2*)(C + (size_t)(r + 8) * ldc + col) = v1;
        }
    }
}

// ---------------------------------------------------------------------------
extern "C" void kernel_launch(void* const* d_in, const int* in_sizes, int n_in,
                              void* d_out, int out_size) {
    const float* x    = (const float*)d_in[0];
    const float* gate = (const float*)d_in[1];
    const float* shw  = (const float*)d_in[2];
    const float* shb  = (const float*)d_in[3];
    const float* u    = (const float*)d_in[4];
    const float* svh  = (const float*)d_in[5];
    const float* eb   = (const float*)d_in[6];
    float* out = (float*)d_out;

    static cudaStream_t s1, s2;
    static cudaEvent_t e0, e1, e2;
    static int once = 0;
    if (!once) {
        cudaStreamCreateWithFlags(&s1, cudaStreamNonBlocking);
        cudaStreamCreateWithFlags(&s2, cudaStreamNonBlocking);
        cudaEventCreateWithFlags(&e0, cudaEventDisableTiming);
        cudaEventCreateWithFlags(&e1, cudaEventDisableTiming);
        cudaEventCreateWithFlags(&e2, cudaEventDisableTiming);
        cudaFuncSetAttribute(ttgemm, cudaFuncAttributeMaxDynamicSharedMemorySize, TSMEM);
        cudaFuncSetAttribute(seg0_gemm,
                             cudaFuncAttributePreferredSharedMemoryCarveout, 100);
        cudaFuncSetAttribute(exp_gemm,
                             cudaFuncAttributePreferredSharedMemoryCarveout, 100);
        once = 1;
    }

    // fork
    cudaEventRecord(e0, 0);
    cudaStreamWaitEvent(s1, e0, 0);
    cudaStreamWaitEvent(s2, e0, 0);

    // s1: small chain -> aext
    bext_kernel<<<(DOUT * KEXT + 255) / 256, 256, 0, s1>>>(u, eb);
    skgemm<<<dim3(N2 / 64, TT / 128, KSPL), 256, 0, s1>>>(x, svh, gate);
    rl_kernel<<<(TT * NE + 255) / 256, 256, 0, s1>>>();
    finalize_w<<<(TT + 255) / 256, 256, 0, s1>>>();
    aext_build<<<(TT * (KEXT / 4) + 255) / 256, 256, 0, s1>>>();
    cudaEventRecord(e1, s1);

    // s2: tf32 mma half (cols [CSPL,4096)) then its expert add
    ttgemm<<<dim3((DOUT - CSPL) / 128, TT / 256), 256, TSMEM, s2>>>(
        x, shw + (size_t)CSPL * DIN, DIN, DIN, DIN / 32,
        out + CSPL, DOUT, shb + CSPL);
    cudaStreamWaitEvent(s2, e1, 0);
    exp_gemm<<<dim3((DOUT - CSPL) / 128, TT / 128), 256, 0, s2>>>(out, CSPL);
    cudaEventRecord(e2, s2);

    // default: FFMA2 half (cols [0,CSPL)) then its expert add
    seg0_gemm<<<dim3(CSPL / 128, TT / 128), 256>>>(x, shw, shb, out);
    cudaStreamWaitEvent(0, e1, 0);
    exp_gemm<<<dim3(CSPL / 128, TT / 128), 256>>>(out, 0);

    // join s2 back to origin
    cudaStreamWaitEvent(0, e2, 0);
}

// round 17
// speedup vs baseline: 7.0541x; 1.0266x over previous
#include <cuda_runtime.h>
#include <cstdint>
#include <math.h>

// Problem constants
#define TT    4096
#define DIN   4096
#define DOUT  4096
#define NE    8
#define N2    320    // [svh(256) | gate(64)]
#define KEXT  272    // 256 + 8 (w->bias) + 8 zero pad -> 17 chunks of 16
#define KSPL  4
#define CSPL  1920   // cols [0,CSPL) FFMA2, [CSPL,4096) tf32 mma

// Scratch (device globals; allocation is forbidden)
__device__ float g_p[KSPL * TT * N2];
__device__ float g_rl[TT * NE];
__device__ float g_w[TT * NE];
__device__ float g_aext[TT * KEXT];
__device__ float g_bext[DOUT * KEXT];

// ---------------- f32x2 packed-FMA helpers ----------
__device__ __forceinline__ void fma2(uint64_t& d, uint64_t a, uint64_t b) {
    asm("fma.rn.f32x2 %0, %1, %2, %0;" : "+l"(d) : "l"(a), "l"(b));
}
__device__ __forceinline__ uint64_t dup32(float v) {
    uint64_t r;
    asm("mov.b64 %0, {%1, %1};" : "=l"(r) : "f"(v));
    return r;
}
__device__ __forceinline__ float2 unpk(uint64_t v) {
    float2 r;
    asm("mov.b64 {%0, %1}, %2;" : "=f"(r.x), "=f"(r.y) : "l"(v));
    return r;
}
// ---------------- tf32 mma helpers ----------
__device__ __forceinline__ uint32_t smem_u32(const void* p) {
    uint32_t a;
    asm("{ .reg .u64 t; cvta.to.shared.u64 t, %1; cvt.u32.u64 %0, t; }" : "=r"(a) : "l"(p));
    return a;
}
__device__ __forceinline__ void cpa16(uint32_t dst, const void* src) {
    asm volatile("cp.async.cg.shared.global [%0], [%1], 16;" :: "r"(dst), "l"(src));
}
__device__ __forceinline__ uint32_t f2tf32(float f) {
    uint32_t r;
    asm("cvt.rna.tf32.f32 %0, %1;" : "=r"(r) : "f"(f));
    return r;
}
__device__ __forceinline__ void mma8(float* c, const uint32_t* a, const uint32_t* b) {
    asm volatile(
        "mma.sync.aligned.m16n8k8.row.col.f32.tf32.tf32.f32 "
        "{%0,%1,%2,%3}, {%4,%5,%6,%7}, {%8,%9}, {%0,%1,%2,%3};"
        : "+f"(c[0]), "+f"(c[1]), "+f"(c[2]), "+f"(c[3])
        : "r"(a[0]), "r"(a[1]), "r"(a[2]), "r"(a[3]), "r"(b[0]), "r"(b[1]));
}

// ---------------------------------------------------------------------------
__global__ void bext_kernel(const float* __restrict__ u, const float* __restrict__ eb) {
    int idx = blockIdx.x * blockDim.x + threadIdx.x;
    if (idx >= DOUT * KEXT) return;
    int n = idx / KEXT;
    int k = idx - n * KEXT;
    float v = 0.f;
    if (k < 256) {
        int e = k >> 5, r = k & 31;
        v = u[(e * DOUT + n) * 32 + r];
    } else if (k < 264) {
        v = eb[(k - 256) * DOUT + n];
    }
    g_bext[idx] = v;
}

// ---------------------------------------------------------------------------
// Split-K fused small GEMM (R12-proven verbatim)
// ---------------------------------------------------------------------------
__global__ __launch_bounds__(256) void skgemm(const float* __restrict__ A,
                                              const float* __restrict__ svh,
                                              const float* __restrict__ gate) {
    constexpr int BK = 16;
    constexpr int LAs = 132, LBs = 68;
    __shared__ float As[2][BK][LAs];
    __shared__ float Bs[2][BK][LBs];
    const int tid = threadIdx.x;
    const int tx = tid & 15, ty = tid >> 4;
    const int arow = tid >> 2;
    const int acol = (tid & 3) * 4;
    const int n0 = blockIdx.x * 64;
    const int t0 = blockIdx.y * 128;
    const int koff = blockIdx.z * (DIN / KSPL);

    const float* Ag = A + (size_t)(t0 + arow) * DIN + koff + acol;
    const float* Bg = (blockIdx.x < 4)
                    ? svh + (size_t)(n0 + arow) * DIN + koff + acol
                    : gate + (size_t)arow * DIN + koff + acol;

    uint64_t acc[4][4];
    #pragma unroll
    for (int i = 0; i < 4; i++)
        #pragma unroll
        for (int j = 0; j < 4; j++) acc[i][j] = 0ull;

    float4 av[2], bv;
    auto sts = [&](int buf) {
        #pragma unroll
        for (int p = 0; p < 2; p++) {
            As[buf][acol + 0][arow + p * 64] = av[p].x;
            As[buf][acol + 1][arow + p * 64] = av[p].y;
            As[buf][acol + 2][arow + p * 64] = av[p].z;
            As[buf][acol + 3][arow + p * 64] = av[p].w;
        }
        Bs[buf][acol + 0][arow] = bv.x;
        Bs[buf][acol + 1][arow] = bv.y;
        Bs[buf][acol + 2][arow] = bv.z;
        Bs[buf][acol + 3][arow] = bv.w;
    };

    av[0] = *(const float4*)(Ag);
    av[1] = *(const float4*)(Ag + (size_t)64 * DIN);
    bv = *(const float4*)(Bg);
    sts(0);
    __syncthreads();

    const int nk = DIN / KSPL / BK;
    for (int kt = 0; kt < nk; kt++) {
        const int cur = kt & 1;
        if (kt + 1 < nk) {
            av[0] = *(const float4*)(Ag + (kt + 1) * BK);
            av[1] = *(const float4*)(Ag + (kt + 1) * BK + (size_t)64 * DIN);
            bv = *(const float4*)(Bg + (kt + 1) * BK);
        }
        #pragma unroll
        for (int kk = 0; kk < BK; kk++) {
            uint64_t a2[4], bd[4];
            {
                ulonglong2 p0 = *(const ulonglong2*)&As[cur][kk][ty * 8];
                ulonglong2 p1 = *(const ulonglong2*)&As[cur][kk][ty * 8 + 4];
                a2[0] = p0.x; a2[1] = p0.y; a2[2] = p1.x; a2[3] = p1.y;
            }
            #pragma unroll
            for (int j = 0; j < 4; j++)
                bd[j] = dup32(Bs[cur][kk][tx * 4 + j]);
            #pragma unroll
            for (int i = 0; i < 4; i++)
                #pragma unroll
                for (int j = 0; j < 4; j++)
                    fma2(acc[i][j], a2[i], bd[j]);
        }
        if (kt + 1 < nk) {
            sts(cur ^ 1);
            __syncthreads();
        }
    }

    float* outp = g_p + (size_t)blockIdx.z * TT * N2;
    const int row0 = t0 + ty * 8;
    const int col0 = n0 + tx * 4;
    #pragma unroll
    for (int i = 0; i < 4; i++)
        #pragma unroll
        for (int j = 0; j < 4; j++) {
            float2 v = unpk(acc[i][j]);
            outp[(size_t)(row0 + 2 * i) * N2 + col0 + j] = v.x;
            outp[(size_t)(row0 + 2 * i + 1) * N2 + col0 + j] = v.y;
        }
}

// ---------------------------------------------------------------------------
__global__ void rl_kernel() {
    int idx = blockIdx.x * blockDim.x + threadIdx.x;
    if (idx >= TT * NE) return;
    int t = idx >> 3, e = idx & 7;
    const float* p0 = g_p + (size_t)t * N2 + 256 + e * 8;
    float s = 0.f;
    #pragma unroll
    for (int r = 0; r < 8; r++) {
        float gl = 0.f;
        #pragma unroll
        for (int ks = 0; ks < KSPL; ks++)
            gl += p0[(size_t)ks * TT * N2 + r];
        s += gl * gl;
    }
    g_rl[idx] = sqrtf(s);
}

__global__ void finalize_w() {
    int t = blockIdx.x * blockDim.x + threadIdx.x;
    if (t >= TT) return;
    float rl[NE];
    #pragma unroll
    for (int e = 0; e < NE; e++) rl[e] = g_rl[t * NE + e];
    int i1 = 0;
    #pragma unroll
    for (int e = 1; e < NE; e++) if (rl[e] > rl[i1]) i1 = e;
    int i2 = (i1 == 0) ? 1 : 0;
    #pragma unroll
    for (int e = 0; e < NE; e++) if (e != i1 && rl[e] > rl[i2]) i2 = e;
    float e2 = expf(rl[i2] - rl[i1]);
    float inv = 1.f / (1.f + e2);
    #pragma unroll
    for (int e = 0; e < NE; e++)
        g_w[t * NE + e] = (e == i1) ? inv : ((e == i2) ? e2 * inv : 0.f);
}

__global__ void aext_build() {
    int idx = blockIdx.x * blockDim.x + threadIdx.x;
    if (idx >= TT * (KEXT / 4)) return;
    int t = idx / (KEXT / 4);
    int k4 = idx - t * (KEXT / 4);
    float4 v;
    if (k4 < 64) {
        const float* p0 = g_p + (size_t)t * N2 + k4 * 4;
        v = *(const float4*)(p0);
        #pragma unroll
        for (int ks = 1; ks < KSPL; ks++) {
            float4 sp = *(const float4*)(p0 + (size_t)ks * TT * N2);
            v.x += sp.x; v.y += sp.y; v.z += sp.z; v.w += sp.w;
        }
        float we = g_w[t * NE + (k4 >> 3)];
        v.x *= we; v.y *= we; v.z *= we; v.w *= we;
    } else if (k4 < 66) {
        const float* wp = g_w + t * NE + (k4 - 64) * 4;
        v = make_float4(wp[0], wp[1], wp[2], wp[3]);
    } else {
        v = make_float4(0.f, 0.f, 0.f, 0.f);
    }
    *(float4*)(g_aext + (size_t)t * KEXT + k4 * 4) = v;
}

// ---------------------------------------------------------------------------
// FFMA2 shared-path GEMM, cols [0, CSPL) (R10/R12-proven structure)
// ---------------------------------------------------------------------------
#define LA 132
#define LBR 144

__global__ __launch_bounds__(256, 2) void seg0_gemm(const float* __restrict__ X,
                                                    const float* __restrict__ W,
                                                    const float* __restrict__ Bias,
                                                    float* __restrict__ C) {
    constexpr int BK = 16;
    __shared__ __align__(16) float As[2][BK][LA];
    __shared__ __align__(16) float Bs[2][BK][LBR];
    const int tid = threadIdx.x;
    const int tx = tid & 15, ty = tid >> 4;
    const int arow = tid >> 2;
    const int acol = (tid & 3) * 4;
    const int bslot = ((arow >> 3) * 9) + (arow & 7);

    uint64_t acc[4][8];
    #pragma unroll
    for (int i = 0; i < 4; i++)
        #pragma unroll
        for (int j = 0; j < 8; j++) acc[i][j] = 0ull;

    float4 av[2], bv[2];
    auto sts = [&](int buf) {
        #pragma unroll
        for (int p = 0; p < 2; p++) {
            As[buf][acol + 0][arow + p * 64] = av[p].x;
            As[buf][acol + 1][arow + p * 64] = av[p].y;
            As[buf][acol + 2][arow + p * 64] = av[p].z;
            As[buf][acol + 3][arow + p * 64] = av[p].w;
            Bs[buf][acol + 0][bslot + p * 72] = bv[p].x;
            Bs[buf][acol + 1][bslot + p * 72] = bv[p].y;
            Bs[buf][acol + 2][bslot + p * 72] = bv[p].z;
            Bs[buf][acol + 3][bslot + p * 72] = bv[p].w;
        }
    };

    const float* Ag = X + (size_t)(blockIdx.y * 128 + arow) * DIN + acol;
    const float* Bg = W + (size_t)(blockIdx.x * 128 + arow) * DIN + acol;

    av[0] = *(const float4*)(Ag);
    av[1] = *(const float4*)(Ag + (size_t)64 * DIN);
    bv[0] = *(const float4*)(Bg);
    bv[1] = *(const float4*)(Bg + (size_t)64 * DIN);
    sts(0);
    __syncthreads();

    const int nk = DIN / BK;
    for (int kt = 0; kt < nk; kt++) {
        const int cur = kt & 1;
        if (kt + 1 < nk) {
            av[0] = *(const float4*)(Ag + (kt + 1) * BK);
            av[1] = *(const float4*)(Ag + (kt + 1) * BK + (size_t)64 * DIN);
            bv[0] = *(const float4*)(Bg + (kt + 1) * BK);
            bv[1] = *(const float4*)(Bg + (kt + 1) * BK + (size_t)64 * DIN);
        }
        #pragma unroll
        for (int kk = 0; kk < BK; kk++) {
            uint64_t a2[4], bd[8];
            {
                ulonglong2 p0 = *(const ulonglong2*)&As[cur][kk][ty * 8];
                ulonglong2 p1 = *(const ulonglong2*)&As[cur][kk][ty * 8 + 4];
                a2[0] = p0.x; a2[1] = p0.y; a2[2] = p1.x; a2[3] = p1.y;
            }
            #pragma unroll
            for (int j = 0; j < 8; j++)
                bd[j] = dup32(Bs[cur][kk][tx * 9 + j]);
            #pragma unroll
            for (int i = 0; i < 4; i++)
                #pragma unroll
                for (int j = 0; j < 8; j++)
                    fma2(acc[i][j], a2[i], bd[j]);
        }
        if (kt + 1 < nk) {
            sts(cur ^ 1);
            __syncthreads();
        }
    }

    const int row0 = blockIdx.y * 128 + ty * 8;
    const int col0 = blockIdx.x * 128 + tx * 8;
    #pragma unroll
    for (int i = 0; i < 4; i++)
        #pragma unroll
        for (int j = 0; j < 8; j++) {
            float2 v = unpk(acc[i][j]);
            float b = Bias[col0 + j];
            C[(size_t)(row0 + 2 * i) * DOUT + col0 + j] = v.x + b;
            C[(size_t)(row0 + 2 * i + 1) * DOUT + col0 + j] = v.y + b;
        }
}

// ---------------------------------------------------------------------------
// FFMA2 expert add-GEMM: out += aext @ bext^T (K=272), cols [coff + 128*bx).
// ---------------------------------------------------------------------------
__global__ __launch_bounds__(256, 2) void exp_gemm(float* __restrict__ C, int coff) {
    constexpr int BK = 16;
    __shared__ __align__(16) float As[2][BK][LA];
    __shared__ __align__(16) float Bs[2][BK][LBR];
    const int tid = threadIdx.x;
    const int tx = tid & 15, ty = tid >> 4;
    const int arow = tid >> 2;
    const int acol = (tid & 3) * 4;
    const int bslot = ((arow >> 3) * 9) + (arow & 7);
    const int nb0 = coff + blockIdx.x * 128;

    uint64_t acc[4][8];
    #pragma unroll
    for (int i = 0; i < 4; i++)
        #pragma unroll
        for (int j = 0; j < 8; j++) acc[i][j] = 0ull;

    float4 av[2], bv[2];
    auto sts = [&](int buf) {
        #pragma unroll
        for (int p = 0; p < 2; p++) {
            As[buf][acol + 0][arow + p * 64] = av[p].x;
            As[buf][acol + 1][arow + p * 64] = av[p].y;
            As[buf][acol + 2][arow + p * 64] = av[p].z;
            As[buf][acol + 3][arow + p * 64] = av[p].w;
            Bs[buf][acol + 0][bslot + p * 72] = bv[p].x;
            Bs[buf][acol + 1][bslot + p * 72] = bv[p].y;
            Bs[buf][acol + 2][bslot + p * 72] = bv[p].z;
            Bs[buf][acol + 3][bslot + p * 72] = bv[p].w;
        }
    };

    const float* Ag = g_aext + (size_t)(blockIdx.y * 128 + arow) * KEXT + acol;
    const float* Bg = g_bext + (size_t)(nb0 + arow) * KEXT + acol;

    av[0] = *(const float4*)(Ag);
    av[1] = *(const float4*)(Ag + (size_t)64 * KEXT);
    bv[0] = *(const float4*)(Bg);
    bv[1] = *(const float4*)(Bg + (size_t)64 * KEXT);
    sts(0);
    __syncthreads();

    const int nk = KEXT / BK;   // 17
    for (int kt = 0; kt < nk; kt++) {
        const int cur = kt & 1;
        if (kt + 1 < nk) {
            av[0] = *(const float4*)(Ag + (kt + 1) * BK);
            av[1] = *(const float4*)(Ag + (kt + 1) * BK + (size_t)64 * KEXT);
            bv[0] = *(const float4*)(Bg + (kt + 1) * BK);
            bv[1] = *(const float4*)(Bg + (kt + 1) * BK + (size_t)64 * KEXT);
        }
        #pragma unroll
        for (int kk = 0; kk < BK; kk++) {
            uint64_t a2[4], bd[8];
            {
                ulonglong2 p0 = *(const ulonglong2*)&As[cur][kk][ty * 8];
                ulonglong2 p1 = *(const ulonglong2*)&As[cur][kk][ty * 8 + 4];
                a2[0] = p0.x; a2[1] = p0.y; a2[2] = p1.x; a2[3] = p1.y;
            }
            #pragma unroll
            for (int j = 0; j < 8; j++)
                bd[j] = dup32(Bs[cur][kk][tx * 9 + j]);
            #pragma unroll
            for (int i = 0; i < 4; i++)
                #pragma unroll
                for (int j = 0; j < 8; j++)
                    fma2(acc[i][j], a2[i], bd[j]);
        }
        if (kt + 1 < nk) {
            sts(cur ^ 1);
            __syncthreads();
        }
    }

    const int row0 = blockIdx.y * 128 + ty * 8;
    const int col0 = nb0 + tx * 8;
    #pragma unroll
    for (int i = 0; i < 4; i++)
        #pragma unroll
        for (int j = 0; j < 8; j++) {
            float2 v = unpk(acc[i][j]);
            C[(size_t)(row0 + 2 * i) * DOUT + col0 + j] += v.x;
            C[(size_t)(row0 + 2 * i + 1) * DOUT + col0 + j] += v.y;
        }
}

// ---------------------------------------------------------------------------
// tf32 mma.sync GEMM, R17: 4-stage cp.async pipeline (loads issued 3 chunks
// ahead, wait_group 2 keeps two groups in flight). cvt in loop.
// ---------------------------------------------------------------------------
#define TSS 36
#define TSTAGE ((256 + 128) * TSS)
#define TSMEM (4 * TSTAGE * 4)

__global__ __launch_bounds__(256, 1)
void ttgemm(const float* __restrict__ A, const float* __restrict__ B,
            int lda, int ldb, int nch,
            float* __restrict__ C, int ldc, const float* __restrict__ bias) {
    extern __shared__ __align__(16) float sm[];
    const int tid = threadIdx.x;
    const int m0 = blockIdx.y * 256, n0 = blockIdx.x * 128;

    auto load_stage = [&](int c, int buf) {
        const int kc0 = c * 32;
        float* sA = sm + buf * TSTAGE;
        float* sB = sA + 256 * TSS;
        #pragma unroll
        for (int i = 0; i < 8; i++) {
            int idx = tid + i * 256;
            int m = idx >> 3, kc = (idx & 7) * 4;
            cpa16(smem_u32(sA + m * TSS + kc), A + (size_t)(m0 + m) * lda + kc0 + kc);
        }
        #pragma unroll
        for (int i = 0; i < 4; i++) {
            int idx = tid + i * 256;
            int nn = idx >> 3, kc = (idx & 7) * 4;
            cpa16(smem_u32(sB + nn * TSS + kc), B + (size_t)(n0 + nn) * ldb + kc0 + kc);
        }
        asm volatile("cp.async.commit_group;" ::: "memory");
    };

    float acc[4][8][4];
    #pragma unroll
    for (int i = 0; i < 4; i++)
        #pragma unroll
        for (int j = 0; j < 8; j++)
            #pragma unroll
            for (int q = 0; q < 4; q++) acc[i][j][q] = 0.f;

    const int warp = tid >> 5, lane = tid & 31;
    const int qr = lane >> 2, qc = lane & 3;
    const int wm = warp >> 1, wn = warp & 1;

    load_stage(0, 0);
    load_stage(1, 1);
    load_stage(2, 2);

    #pragma unroll 1
    for (int c = 0; c < nch; c++) {
        const int buf = c & 3;
        if (c + 2 < nch)      asm volatile("cp.async.wait_group 2;" ::: "memory");
        else if (c + 1 < nch) asm volatile("cp.async.wait_group 1;" ::: "memory");
        else                  asm volatile("cp.async.wait_group 0;" ::: "memory");
        __syncthreads();
        // issue load c+3 BEFORE compute c: its buffer (c+3)&3 == (c-1)&3 was
        // last read in compute c-1, which all threads passed at the sync.
        if (c + 3 < nch) load_stage(c + 3, (c + 3) & 3);

        const float* sA = sm + buf * TSTAGE + (wm * 64 + qr) * TSS + qc;
        const float* sB = sm + buf * TSTAGE + 256 * TSS + (wn * 64 + qr) * TSS + qc;

        #pragma unroll
        for (int kk = 0; kk < 4; kk++) {
            uint32_t af[4][4], bf[8][2];
            #pragma unroll
            for (int mt = 0; mt < 4; mt++) {
                const float* p = sA + mt * 16 * TSS + kk * 8;
                af[mt][0] = f2tf32(p[0]);
                af[mt][1] = f2tf32(p[8 * TSS]);
                af[mt][2] = f2tf32(p[4]);
                af[mt][3] = f2tf32(p[8 * TSS + 4]);
            }
            #pragma unroll
            for (int nt = 0; nt < 8; nt++) {
                const float* p = sB + nt * 8 * TSS + kk * 8;
                bf[nt][0] = f2tf32(p[0]);
                bf[nt][1] = f2tf32(p[4]);
            }
            #pragma unroll
            for (int mt = 0; mt < 4; mt++)
                #pragma unroll
                for (int nt = 0; nt < 8; nt++)
                    mma8(acc[mt][nt], af[mt], bf[nt]);
        }
    }

    const int rbase = m0 + wm * 64;
    const int cbase = n0 + wn * 64;
    #pragma unroll
    for (int mt = 0; mt < 4; mt++) {
        #pragma unroll
        for (int nt = 0; nt < 8; nt++) {
            const int r = rbase + mt * 16 + qr;
            const int col = cbase + nt * 8 + qc * 2;
            float bx = bias[col], by = bias[col + 1];
            float2 v0 = make_float2(acc[mt][nt][0] + bx, acc[mt][nt][1] + by);
            float2 v1 = make_float2(acc[mt][nt][2] + bx, acc[mt][nt][3] + by);
            *(float2*)(C + (size_t)r * ldc + col) = v0;
            *(float2*)(C + (size_t)(r + 8) * ldc + col) = v1;
        }
    }
}

// ---------------------------------------------------------------------------
extern "C" void kernel_launch(void* const* d_in, const int* in_sizes, int n_in,
                              void* d_out, int out_size) {
    const float* x    = (const float*)d_in[0];
    const float* gate = (const float*)d_in[1];
    const float* shw  = (const float*)d_in[2];
    const float* shb  = (const float*)d_in[3];
    const float* u    = (const float*)d_in[4];
    const float* svh  = (const float*)d_in[5];
    const float* eb   = (const float*)d_in[6];
    float* out = (float*)d_out;

    static cudaStream_t s1, s2;
    static cudaEvent_t e0, e1, e2;
    static int once = 0;
    if (!once) {
        cudaStreamCreateWithFlags(&s1, cudaStreamNonBlocking);
        cudaStreamCreateWithFlags(&s2, cudaStreamNonBlocking);
        cudaEventCreateWithFlags(&e0, cudaEventDisableTiming);
        cudaEventCreateWithFlags(&e1, cudaEventDisableTiming);
        cudaEventCreateWithFlags(&e2, cudaEventDisableTiming);
        cudaFuncSetAttribute(ttgemm, cudaFuncAttributeMaxDynamicSharedMemorySize, TSMEM);
        cudaFuncSetAttribute(seg0_gemm,
                             cudaFuncAttributePreferredSharedMemoryCarveout, 100);
        cudaFuncSetAttribute(exp_gemm,
                             cudaFuncAttributePreferredSharedMemoryCarveout, 100);
        once = 1;
    }

    // fork
    cudaEventRecord(e0, 0);
    cudaStreamWaitEvent(s1, e0, 0);
    cudaStreamWaitEvent(s2, e0, 0);

    // s1: small chain -> aext
    bext_kernel<<<(DOUT * KEXT + 255) / 256, 256, 0, s1>>>(u, eb);
    skgemm<<<dim3(N2 / 64, TT / 128, KSPL), 256, 0, s1>>>(x, svh, gate);
    rl_kernel<<<(TT * NE + 255) / 256, 256, 0, s1>>>();
    finalize_w<<<(TT + 255) / 256, 256, 0, s1>>>();
    aext_build<<<(TT * (KEXT / 4) + 255) / 256, 256, 0, s1>>>();
    cudaEventRecord(e1, s1);

    // s2: tf32 mma half (cols [CSPL,4096)) then its expert add
    ttgemm<<<dim3((DOUT - CSPL) / 128, TT / 256), 256, TSMEM, s2>>>(
        x, shw + (size_t)CSPL * DIN, DIN, DIN, DIN / 32,
        out + CSPL, DOUT, shb + CSPL);
    cudaStreamWaitEvent(s2, e1, 0);
    exp_gemm<<<dim3((DOUT - CSPL) / 128, TT / 128), 256, 0, s2>>>(out, CSPL);
    cudaEventRecord(e2, s2);

    // default: FFMA2 half (cols [0,CSPL)) then its expert add
    seg0_gemm<<<dim3(CSPL / 128, TT / 128), 256>>>(x, shw, shb, out);
    cudaStreamWaitEvent(0, e1, 0);
    exp_gemm<<<dim3(CSPL / 128, TT / 128), 256>>>(out, 0);

    // join s2 back to origin
    cudaStreamWaitEvent(0, e2, 0);
}